// round 1
// baseline (speedup 1.0000x reference)
#include <cuda_runtime.h>

// Problem constants
#define SQ 4096   // sequence length
#define DM 1024   // model dim
#define NH 16     // heads
#define HD 64     // head dim
#define D3 3072   // 3*DM

// Scratch (allocation-free requirement -> device globals)
__device__ float g_qkv[SQ * D3];    // qkv projection output [S, 3D]
__device__ float g_attn[SQ * DM];   // attention output [S, D]

// ---------------------------------------------------------------------------
// SGEMM: C[M,N] = A[M,K] @ B[K,N] + bias[N]
// 128x128 block tile, BK=16, 256 threads, 8x8 micro-tile
// ---------------------------------------------------------------------------
#define BM 128
#define BN 128
#define BK 16
#define TM 8
#define TN 8

__global__ __launch_bounds__(256) void sgemm_bias(
    const float* __restrict__ A, const float* __restrict__ B,
    const float* __restrict__ bias, float* __restrict__ C,
    int M, int N, int K)
{
    __shared__ float As[BK][BM];   // A stored transposed: As[k][m]
    __shared__ float Bs[BK][BN];

    const int tid = threadIdx.x;
    const int bm = blockIdx.y * BM;
    const int bn = blockIdx.x * BN;
    const int trow = (tid / 16) * TM;
    const int tcol = (tid % 16) * TN;

    float acc[TM][TN];
    #pragma unroll
    for (int i = 0; i < TM; i++)
        #pragma unroll
        for (int j = 0; j < TN; j++) acc[i][j] = 0.f;

    // A load mapping: thread -> (row = tid/4 [+64], 4 cols at (tid%4)*4)
    const int arow = tid / 4;
    const int acol = (tid % 4) * 4;
    // B load mapping: thread -> (row = tid/32 [+8], 4 cols at (tid%32)*4)
    const int brow = tid / 32;
    const int bcol = (tid % 32) * 4;

    for (int k0 = 0; k0 < K; k0 += BK) {
        #pragma unroll
        for (int h = 0; h < 2; h++) {
            int r = arow + h * 64;
            float4 a = *(const float4*)(A + (size_t)(bm + r) * K + k0 + acol);
            As[acol + 0][r] = a.x;
            As[acol + 1][r] = a.y;
            As[acol + 2][r] = a.z;
            As[acol + 3][r] = a.w;
        }
        #pragma unroll
        for (int h = 0; h < 2; h++) {
            int r = brow + h * 8;
            float4 b = *(const float4*)(B + (size_t)(k0 + r) * N + bn + bcol);
            *(float4*)(&Bs[r][bcol]) = b;
        }
        __syncthreads();

        #pragma unroll
        for (int kk = 0; kk < BK; kk++) {
            float ra[TM], rb[TN];
            #pragma unroll
            for (int i = 0; i < TM; i++) ra[i] = As[kk][trow + i];
            #pragma unroll
            for (int j = 0; j < TN; j++) rb[j] = Bs[kk][tcol + j];
            #pragma unroll
            for (int i = 0; i < TM; i++)
                #pragma unroll
                for (int j = 0; j < TN; j++)
                    acc[i][j] += ra[i] * rb[j];
        }
        __syncthreads();
    }

    #pragma unroll
    for (int i = 0; i < TM; i++) {
        float* crow = C + (size_t)(bm + trow + i) * N + bn + tcol;
        #pragma unroll
        for (int j = 0; j < TN; j += 4) {
            float4 o;
            o.x = acc[i][j + 0] + bias[bn + tcol + j + 0];
            o.y = acc[i][j + 1] + bias[bn + tcol + j + 1];
            o.z = acc[i][j + 2] + bias[bn + tcol + j + 2];
            o.w = acc[i][j + 3] + bias[bn + tcol + j + 3];
            *(float4*)(crow + j) = o;
        }
    }
}

// ---------------------------------------------------------------------------
// Flash attention (fp32, causal). One block = (head, 64-query tile).
// 256 threads in 16x16 layout, each owning a 4x4 fragment of the 64x64 tiles.
// smem: Qs[64][64], Kst[64 dims][64 keys], Vs[64 keys][64 dims], Ps[64][64]
// ---------------------------------------------------------------------------
#define QT 64
#define KT 64
#define ATT_SMEM (4 * 64 * 64 * 4)

__global__ __launch_bounds__(256) void flash_attn(
    const float* __restrict__ qkv, float* __restrict__ out)
{
    extern __shared__ float sm[];
    float* Qs  = sm;                  // [64][64] row-major (q, d)
    float* Kst = sm + 64 * 64;        // [64][64] dim-major  (d, key)
    float* Vs  = sm + 2 * 64 * 64;    // [64][64] row-major (key, d)
    float* Ps  = sm + 3 * 64 * 64;    // [64][64] row-major (q, key)

    const int tid = threadIdx.x;
    const int ty = tid / 16;          // query group (4 rows)
    const int tx = tid % 16;          // key/dim group (4 cols)
    const int h  = blockIdx.y;
    const int qt = blockIdx.x;
    const int q0 = qt * QT;

    const float* qbase = qkv + h * HD;             // + row*D3
    const float* kbase = qkv + DM + h * HD;
    const float* vbase = qkv + 2 * DM + h * HD;

    // Load Q tile: 64x64 floats = 1024 float4, 4 per thread
    for (int idx = tid; idx < 1024; idx += 256) {
        int r = idx / 16;
        int c = (idx % 16) * 4;
        float4 qv = *(const float4*)(qbase + (size_t)(q0 + r) * D3 + c);
        *(float4*)(Qs + r * 64 + c) = qv;
    }
    __syncthreads();

    float m[4], l[4], o[4][4];
    #pragma unroll
    for (int i = 0; i < 4; i++) {
        m[i] = -1e30f;
        l[i] = 0.f;
        #pragma unroll
        for (int j = 0; j < 4; j++) o[i][j] = 0.f;
    }

    const float scale = 0.125f;  // 1/sqrt(64)

    for (int kt = 0; kt <= qt; kt++) {
        // Load K (transposed to dim-major) and V (natural) tiles
        for (int idx = tid; idx < 1024; idx += 256) {
            int r = idx / 16;          // key within tile
            int c = (idx % 16) * 4;    // dim
            size_t grow = (size_t)(kt * KT + r) * D3;
            float4 kv = *(const float4*)(kbase + grow + c);
            Kst[(c + 0) * 64 + r] = kv.x;
            Kst[(c + 1) * 64 + r] = kv.y;
            Kst[(c + 2) * 64 + r] = kv.z;
            Kst[(c + 3) * 64 + r] = kv.w;
            float4 vv = *(const float4*)(vbase + grow + c);
            *(float4*)(Vs + r * 64 + c) = vv;
        }
        __syncthreads();

        // S tile = Q @ K^T (64x64x64)
        float s[4][4];
        #pragma unroll
        for (int i = 0; i < 4; i++)
            #pragma unroll
            for (int j = 0; j < 4; j++) s[i][j] = 0.f;

        #pragma unroll 4
        for (int d = 0; d < 64; d++) {
            float qa[4];
            #pragma unroll
            for (int i = 0; i < 4; i++) qa[i] = Qs[(4 * ty + i) * 64 + d];
            float4 kb = *(float4*)(Kst + d * 64 + 4 * tx);
            #pragma unroll
            for (int i = 0; i < 4; i++) {
                s[i][0] += qa[i] * kb.x;
                s[i][1] += qa[i] * kb.y;
                s[i][2] += qa[i] * kb.z;
                s[i][3] += qa[i] * kb.w;
            }
        }

        // scale + causal mask (only diagonal tile needs masking)
        #pragma unroll
        for (int i = 0; i < 4; i++)
            #pragma unroll
            for (int j = 0; j < 4; j++) {
                s[i][j] *= scale;
                if (kt == qt && (4 * tx + j) > (4 * ty + i)) s[i][j] = -1e30f;
            }

        // Online softmax (per query row; row spread over 16 tx threads)
        #pragma unroll
        for (int i = 0; i < 4; i++) {
            float rmax = fmaxf(fmaxf(s[i][0], s[i][1]), fmaxf(s[i][2], s[i][3]));
            #pragma unroll
            for (int off = 8; off > 0; off >>= 1)
                rmax = fmaxf(rmax, __shfl_xor_sync(0xffffffffu, rmax, off, 16));
            float mnew = fmaxf(m[i], rmax);
            float alpha = __expf(m[i] - mnew);
            float rsum = 0.f;
            #pragma unroll
            for (int j = 0; j < 4; j++) {
                float p = __expf(s[i][j] - mnew);
                Ps[(4 * ty + i) * 64 + 4 * tx + j] = p;
                rsum += p;
            }
            #pragma unroll
            for (int off = 8; off > 0; off >>= 1)
                rsum += __shfl_xor_sync(0xffffffffu, rsum, off, 16);
            l[i] = l[i] * alpha + rsum;
            m[i] = mnew;
            #pragma unroll
            for (int j = 0; j < 4; j++) o[i][j] *= alpha;
        }
        __syncthreads();  // Ps visible to all

        // O += P @ V (64x64x64)
        #pragma unroll 4
        for (int kk = 0; kk < 64; kk++) {
            float pa[4];
            #pragma unroll
            for (int i = 0; i < 4; i++) pa[i] = Ps[(4 * ty + i) * 64 + kk];
            float4 vb = *(float4*)(Vs + kk * 64 + 4 * tx);
            #pragma unroll
            for (int i = 0; i < 4; i++) {
                o[i][0] += pa[i] * vb.x;
                o[i][1] += pa[i] * vb.y;
                o[i][2] += pa[i] * vb.z;
                o[i][3] += pa[i] * vb.w;
            }
        }
        __syncthreads();  // Vs/Ps consumed; safe to overwrite next iter
    }

    // Normalize and write out: out[q, h*HD + d]
    #pragma unroll
    for (int i = 0; i < 4; i++) {
        float inv = 1.f / l[i];
        int row = q0 + 4 * ty + i;
        float4 ov;
        ov.x = o[i][0] * inv;
        ov.y = o[i][1] * inv;
        ov.z = o[i][2] * inv;
        ov.w = o[i][3] * inv;
        *(float4*)(out + (size_t)row * DM + h * HD + 4 * tx) = ov;
    }
}

// ---------------------------------------------------------------------------
// Launch
// ---------------------------------------------------------------------------
extern "C" void kernel_launch(void* const* d_in, const int* in_sizes, int n_in,
                              void* d_out, int out_size)
{
    const float* x     = (const float*)d_in[0];   // [S, D]
    const float* Wqkv  = (const float*)d_in[1];   // [D, 3D]
    const float* bqkv  = (const float*)d_in[2];   // [3D]
    const float* Wout  = (const float*)d_in[3];   // [D, D]
    const float* bout  = (const float*)d_in[4];   // [D]
    float* out = (float*)d_out;                   // [S, D]

    float* qkv  = nullptr;
    float* attn = nullptr;
    cudaGetSymbolAddress((void**)&qkv,  g_qkv);
    cudaGetSymbolAddress((void**)&attn, g_attn);

    // 1) QKV projection: [S,3D] = x @ Wqkv + bqkv
    {
        dim3 grid(D3 / BN, SQ / BM);
        sgemm_bias<<<grid, 256>>>(x, Wqkv, bqkv, qkv, SQ, D3, DM);
    }

    // 2) Flash attention
    {
        cudaFuncSetAttribute(flash_attn,
                             cudaFuncAttributeMaxDynamicSharedMemorySize,
                             ATT_SMEM);
        dim3 grid(SQ / QT, NH);
        flash_attn<<<grid, 256, ATT_SMEM>>>(qkv, attn);
    }

    // 3) Output projection: [S,D] = attn @ Wout + bout
    {
        dim3 grid(DM / BN, SQ / BM);
        sgemm_bias<<<grid, 256>>>(attn, Wout, bout, out, SQ, DM, DM);
    }
}

// round 2
// speedup vs baseline: 3.1567x; 3.1567x over previous
#include <cuda_runtime.h>
#include <cstdint>

#define SQ 4096
#define DM 1024
#define NH 16
#define HD 64
#define D3 3072

__device__ float g_qkv[SQ * D3];
__device__ float g_attn[SQ * DM];

// ---------------------------------------------------------------------------
// tf32 helpers
// ---------------------------------------------------------------------------
__device__ __forceinline__ uint32_t f2tf(float x) {
    uint32_t r;
    asm("cvt.rna.tf32.f32 %0, %1;" : "=r"(r) : "f"(x));
    return r;
}

__device__ __forceinline__ void mma_tf32(float* d, const uint32_t* a,
                                         const uint32_t* b, const float* c) {
    asm volatile(
        "mma.sync.aligned.m16n8k8.row.col.f32.tf32.tf32.f32 "
        "{%0,%1,%2,%3}, {%4,%5,%6,%7}, {%8,%9}, {%10,%11,%12,%13};"
        : "=f"(d[0]), "=f"(d[1]), "=f"(d[2]), "=f"(d[3])
        : "r"(a[0]), "r"(a[1]), "r"(a[2]), "r"(a[3]),
          "r"(b[0]), "r"(b[1]),
          "f"(c[0]), "f"(c[1]), "f"(c[2]), "f"(c[3]));
}

// ---------------------------------------------------------------------------
// TF32 GEMM: C[M,N] = A[M,K] @ B[K,N] + bias
// 128x128x32 block tile, 256 threads (8 warps, 2x4), warp tile 64x32
// ---------------------------------------------------------------------------
#define GBM 128
#define GBN 128
#define GBK 32
#define APAD 36
#define BPAD 136

__global__ __launch_bounds__(256) void gemm_tf32(
    const float* __restrict__ A, const float* __restrict__ B,
    const float* __restrict__ bias, float* __restrict__ C,
    int M, int N, int K)
{
    __shared__ uint32_t As[GBM * APAD];  // [row][k], pad 36 -> frag LDS conflict-free
    __shared__ uint32_t Bs[GBK * BPAD];  // [k][n],  pad 136 -> frag LDS conflict-free

    const int tid = threadIdx.x;
    const int lane = tid & 31;
    const int w = tid >> 5;
    const int wm = w >> 2;   // 0..1  (64 rows)
    const int wn = w & 3;    // 0..3  (32 cols)
    const int bm = blockIdx.y * GBM;
    const int bn = blockIdx.x * GBN;

    float acc[4][4][4];
    #pragma unroll
    for (int mt = 0; mt < 4; mt++)
        #pragma unroll
        for (int nt = 0; nt < 4; nt++)
            #pragma unroll
            for (int i = 0; i < 4; i++) acc[mt][nt][i] = 0.f;

    const int ar = tid >> 3;          // 0..31 (rows, 4 passes of 32)
    const int ac = (tid & 7) * 4;     // 0..28
    const int br = tid >> 5;          // 0..7  (rows, 4 passes of 8)
    const int bc = (tid & 31) * 4;    // 0..124

    for (int k0 = 0; k0 < K; k0 += GBK) {
        #pragma unroll
        for (int i = 0; i < 4; i++) {
            int r = ar + i * 32;
            float4 av = *(const float4*)(A + (size_t)(bm + r) * K + k0 + ac);
            As[r * APAD + ac + 0] = f2tf(av.x);
            As[r * APAD + ac + 1] = f2tf(av.y);
            As[r * APAD + ac + 2] = f2tf(av.z);
            As[r * APAD + ac + 3] = f2tf(av.w);
        }
        #pragma unroll
        for (int i = 0; i < 4; i++) {
            int r = br + i * 8;
            float4 bv = *(const float4*)(B + (size_t)(k0 + r) * N + bn + bc);
            Bs[r * BPAD + bc + 0] = f2tf(bv.x);
            Bs[r * BPAD + bc + 1] = f2tf(bv.y);
            Bs[r * BPAD + bc + 2] = f2tf(bv.z);
            Bs[r * BPAD + bc + 3] = f2tf(bv.w);
        }
        __syncthreads();

        #pragma unroll
        for (int ks = 0; ks < 4; ks++) {
            uint32_t af[4][4], bf[4][2];
            const int col = ks * 8 + (lane & 3);
            #pragma unroll
            for (int mt = 0; mt < 4; mt++) {
                int row = wm * 64 + mt * 16 + (lane >> 2);
                af[mt][0] = As[row * APAD + col];
                af[mt][1] = As[(row + 8) * APAD + col];
                af[mt][2] = As[row * APAD + col + 4];
                af[mt][3] = As[(row + 8) * APAD + col + 4];
            }
            #pragma unroll
            for (int nt = 0; nt < 4; nt++) {
                int n = wn * 32 + nt * 8 + (lane >> 2);
                bf[nt][0] = Bs[col * BPAD + n];
                bf[nt][1] = Bs[(col + 4) * BPAD + n];
            }
            #pragma unroll
            for (int mt = 0; mt < 4; mt++)
                #pragma unroll
                for (int nt = 0; nt < 4; nt++)
                    mma_tf32(acc[mt][nt], af[mt], bf[nt], acc[mt][nt]);
        }
        __syncthreads();
    }

    #pragma unroll
    for (int mt = 0; mt < 4; mt++) {
        int row = bm + wm * 64 + mt * 16 + (lane >> 2);
        #pragma unroll
        for (int nt = 0; nt < 4; nt++) {
            int col = bn + wn * 32 + nt * 8 + (lane & 3) * 2;
            float b0 = bias[col], b1 = bias[col + 1];
            float2 v0 = make_float2(acc[mt][nt][0] + b0, acc[mt][nt][1] + b1);
            float2 v1 = make_float2(acc[mt][nt][2] + b0, acc[mt][nt][3] + b1);
            *(float2*)(C + (size_t)row * N + col) = v0;
            *(float2*)(C + (size_t)(row + 8) * N + col) = v1;
        }
    }
}

// ---------------------------------------------------------------------------
// Flash attention with tf32 mma. Block = (head, 64-query tile), 128 threads.
// Warp w owns q rows [w*16, w*16+16) -> softmax stats stay within a warp.
// smem: Ks[64][68] (key,d), Vt[64][68] (d,key), Ps[64][68] (q,key / Q staging)
// ---------------------------------------------------------------------------
#define PAD 68
#define AT_SMEM (3 * 64 * PAD * 4)

__global__ __launch_bounds__(128) void attn_tf32(
    const float* __restrict__ qkv, float* __restrict__ out)
{
    extern __shared__ uint32_t sm_[];
    uint32_t* Ks = sm_;
    uint32_t* Vt = sm_ + 64 * PAD;
    uint32_t* Ps = sm_ + 2 * 64 * PAD;

    const int tid = threadIdx.x;
    const int lane = tid & 31;
    const int w = tid >> 5;
    const int h = blockIdx.y;
    const int qt = gridDim.x - 1 - blockIdx.x;  // heaviest tiles first
    const int q0 = qt * 64;

    const float* qb = qkv + h * HD;
    const float* kb = qkv + DM + h * HD;
    const float* vb = qkv + 2 * DM + h * HD;

    // Stage Q through Ps buffer, then preload Q fragments into registers
    for (int idx = tid; idx < 1024; idx += 128) {
        int r = idx >> 4, c = (idx & 15) * 4;
        float4 qv = *(const float4*)(qb + (size_t)(q0 + r) * D3 + c);
        Ps[r * PAD + c + 0] = f2tf(qv.x);
        Ps[r * PAD + c + 1] = f2tf(qv.y);
        Ps[r * PAD + c + 2] = f2tf(qv.z);
        Ps[r * PAD + c + 3] = f2tf(qv.w);
    }
    __syncthreads();

    uint32_t qa[8][4];
    const int qrl = w * 16 + (lane >> 2);  // local q row (first half)
    #pragma unroll
    for (int ks = 0; ks < 8; ks++) {
        int col = ks * 8 + (lane & 3);
        qa[ks][0] = Ps[qrl * PAD + col];
        qa[ks][1] = Ps[(qrl + 8) * PAD + col];
        qa[ks][2] = Ps[qrl * PAD + col + 4];
        qa[ks][3] = Ps[(qrl + 8) * PAD + col + 4];
    }
    __syncthreads();

    float m0 = -1e30f, m1 = -1e30f, l0 = 0.f, l1 = 0.f;
    float o[8][4];
    #pragma unroll
    for (int nt = 0; nt < 8; nt++)
        #pragma unroll
        for (int i = 0; i < 4; i++) o[nt][i] = 0.f;

    const float scale = 0.125f;

    for (int kt = 0; kt <= qt; kt++) {
        // Load K (natural) and V (transposed) tiles, converting to tf32
        for (int idx = tid; idx < 1024; idx += 128) {
            int r = idx >> 4, c = (idx & 15) * 4;
            size_t grow = (size_t)(kt * 64 + r) * D3 + c;
            float4 kv = *(const float4*)(kb + grow);
            Ks[r * PAD + c + 0] = f2tf(kv.x);
            Ks[r * PAD + c + 1] = f2tf(kv.y);
            Ks[r * PAD + c + 2] = f2tf(kv.z);
            Ks[r * PAD + c + 3] = f2tf(kv.w);
            float4 vv = *(const float4*)(vb + grow);
            Vt[(c + 0) * PAD + r] = f2tf(vv.x);
            Vt[(c + 1) * PAD + r] = f2tf(vv.y);
            Vt[(c + 2) * PAD + r] = f2tf(vv.z);
            Vt[(c + 3) * PAD + r] = f2tf(vv.w);
        }
        __syncthreads();

        // S = Q @ K^T : warp slice 16(q) x 64(key), k over d=64
        float s[8][4];
        #pragma unroll
        for (int nt = 0; nt < 8; nt++)
            #pragma unroll
            for (int i = 0; i < 4; i++) s[nt][i] = 0.f;

        #pragma unroll
        for (int ks = 0; ks < 8; ks++) {
            const int d = ks * 8 + (lane & 3);
            #pragma unroll
            for (int nt = 0; nt < 8; nt++) {
                uint32_t bf[2];
                int key = nt * 8 + (lane >> 2);
                bf[0] = Ks[key * PAD + d];
                bf[1] = Ks[key * PAD + d + 4];
                mma_tf32(s[nt], qa[ks], bf, s[nt]);
            }
        }

        // Scale + causal mask (diagonal tile only)
        const int gr0 = q0 + qrl;        // global q row, first half
        const int gr1 = gr0 + 8;
        #pragma unroll
        for (int nt = 0; nt < 8; nt++) {
            int colg = kt * 64 + nt * 8 + (lane & 3) * 2;
            #pragma unroll
            for (int i = 0; i < 4; i++) s[nt][i] *= scale;
            if (kt == qt) {
                if (colg > gr0) s[nt][0] = -1e30f;
                if (colg + 1 > gr0) s[nt][1] = -1e30f;
                if (colg > gr1) s[nt][2] = -1e30f;
                if (colg + 1 > gr1) s[nt][3] = -1e30f;
            }
        }

        // Online softmax: rows spread over 4 lanes (lane&3 quad)
        float mx0 = -1e30f, mx1 = -1e30f;
        #pragma unroll
        for (int nt = 0; nt < 8; nt++) {
            mx0 = fmaxf(mx0, fmaxf(s[nt][0], s[nt][1]));
            mx1 = fmaxf(mx1, fmaxf(s[nt][2], s[nt][3]));
        }
        mx0 = fmaxf(mx0, __shfl_xor_sync(0xffffffffu, mx0, 1));
        mx0 = fmaxf(mx0, __shfl_xor_sync(0xffffffffu, mx0, 2));
        mx1 = fmaxf(mx1, __shfl_xor_sync(0xffffffffu, mx1, 1));
        mx1 = fmaxf(mx1, __shfl_xor_sync(0xffffffffu, mx1, 2));

        float nm0 = fmaxf(m0, mx0), nm1 = fmaxf(m1, mx1);
        float al0 = __expf(m0 - nm0), al1 = __expf(m1 - nm1);
        float sum0 = 0.f, sum1 = 0.f;

        #pragma unroll
        for (int nt = 0; nt < 8; nt++) {
            int kc = nt * 8 + (lane & 3) * 2;
            float p00 = __expf(s[nt][0] - nm0);
            float p01 = __expf(s[nt][1] - nm0);
            float p10 = __expf(s[nt][2] - nm1);
            float p11 = __expf(s[nt][3] - nm1);
            sum0 += p00 + p01;
            sum1 += p10 + p11;
            Ps[qrl * PAD + kc] = f2tf(p00);
            Ps[qrl * PAD + kc + 1] = f2tf(p01);
            Ps[(qrl + 8) * PAD + kc] = f2tf(p10);
            Ps[(qrl + 8) * PAD + kc + 1] = f2tf(p11);
        }
        sum0 += __shfl_xor_sync(0xffffffffu, sum0, 1);
        sum0 += __shfl_xor_sync(0xffffffffu, sum0, 2);
        sum1 += __shfl_xor_sync(0xffffffffu, sum1, 1);
        sum1 += __shfl_xor_sync(0xffffffffu, sum1, 2);

        l0 = l0 * al0 + sum0;
        l1 = l1 * al1 + sum1;
        m0 = nm0;
        m1 = nm1;
        #pragma unroll
        for (int nt = 0; nt < 8; nt++) {
            o[nt][0] *= al0;
            o[nt][1] *= al0;
            o[nt][2] *= al1;
            o[nt][3] *= al1;
        }
        __syncwarp();  // Ps rows written/read only within this warp

        // O += P @ V : a-frags from Ps (own rows), b-frags from Vt
        #pragma unroll
        for (int ks = 0; ks < 8; ks++) {
            uint32_t af[4];
            int kc = ks * 8 + (lane & 3);
            af[0] = Ps[qrl * PAD + kc];
            af[1] = Ps[(qrl + 8) * PAD + kc];
            af[2] = Ps[qrl * PAD + kc + 4];
            af[3] = Ps[(qrl + 8) * PAD + kc + 4];
            #pragma unroll
            for (int nt = 0; nt < 8; nt++) {
                uint32_t bf[2];
                int d = nt * 8 + (lane >> 2);
                bf[0] = Vt[d * PAD + kc];
                bf[1] = Vt[d * PAD + kc + 4];
                mma_tf32(o[nt], af, bf, o[nt]);
            }
        }
        __syncthreads();  // before next iter overwrites Ks/Vt
    }

    // Epilogue: out[q, h*64 + d] = o / l
    float inv0 = 1.f / l0, inv1 = 1.f / l1;
    #pragma unroll
    for (int nt = 0; nt < 8; nt++) {
        int col = h * HD + nt * 8 + (lane & 3) * 2;
        float2 v0 = make_float2(o[nt][0] * inv0, o[nt][1] * inv0);
        float2 v1 = make_float2(o[nt][2] * inv1, o[nt][3] * inv1);
        *(float2*)(out + (size_t)(q0 + qrl) * DM + col) = v0;
        *(float2*)(out + (size_t)(q0 + qrl + 8) * DM + col) = v1;
    }
}

// ---------------------------------------------------------------------------
// Launch
// ---------------------------------------------------------------------------
extern "C" void kernel_launch(void* const* d_in, const int* in_sizes, int n_in,
                              void* d_out, int out_size)
{
    const float* x    = (const float*)d_in[0];
    const float* Wqkv = (const float*)d_in[1];
    const float* bqkv = (const float*)d_in[2];
    const float* Wout = (const float*)d_in[3];
    const float* bout = (const float*)d_in[4];
    float* out = (float*)d_out;

    float* qkv = nullptr;
    float* attn = nullptr;
    cudaGetSymbolAddress((void**)&qkv, g_qkv);
    cudaGetSymbolAddress((void**)&attn, g_attn);

    // 1) QKV projection
    {
        dim3 grid(D3 / GBN, SQ / GBM);
        gemm_tf32<<<grid, 256>>>(x, Wqkv, bqkv, qkv, SQ, D3, DM);
    }

    // 2) Flash attention (tf32 mma)
    {
        static bool attr_set = false;
        cudaFuncSetAttribute(attn_tf32,
                             cudaFuncAttributeMaxDynamicSharedMemorySize,
                             AT_SMEM);
        (void)attr_set;
        dim3 grid(SQ / 64, NH);
        attn_tf32<<<grid, 128, AT_SMEM>>>(qkv, attn);
    }

    // 3) Output projection
    {
        dim3 grid(DM / GBN, SQ / GBM);
        gemm_tf32<<<grid, 256>>>(attn, Wout, bout, out, SQ, DM, DM);
    }
}

// round 3
// speedup vs baseline: 3.6578x; 1.1587x over previous
#include <cuda_runtime.h>
#include <cstdint>

#define SQ 4096
#define DM 1024
#define NH 16
#define HD 64
#define D3 3072

// tf32-bit scratch (allocation-free -> device globals)
__device__ uint32_t g_xt[SQ * DM];
__device__ uint32_t g_wqkvt[DM * D3];
__device__ uint32_t g_woutt[DM * DM];
__device__ uint32_t g_qkv[SQ * D3];
__device__ uint32_t g_attn[SQ * DM];

// ---------------------------------------------------------------------------
// helpers
// ---------------------------------------------------------------------------
__device__ __forceinline__ uint32_t f2tf(float x) {
    uint32_t r;
    asm("cvt.rna.tf32.f32 %0, %1;" : "=r"(r) : "f"(x));
    return r;
}

__device__ __forceinline__ void mma_tf32(float* d, const uint32_t* a,
                                         const uint32_t* b, const float* c) {
    asm volatile(
        "mma.sync.aligned.m16n8k8.row.col.f32.tf32.tf32.f32 "
        "{%0,%1,%2,%3}, {%4,%5,%6,%7}, {%8,%9}, {%10,%11,%12,%13};"
        : "=f"(d[0]), "=f"(d[1]), "=f"(d[2]), "=f"(d[3])
        : "r"(a[0]), "r"(a[1]), "r"(a[2]), "r"(a[3]),
          "r"(b[0]), "r"(b[1]),
          "f"(c[0]), "f"(c[1]), "f"(c[2]), "f"(c[3]));
}

__device__ __forceinline__ void cpa16(uint32_t saddr, const void* gptr) {
    asm volatile("cp.async.cg.shared.global [%0], [%1], 16;"
                 :: "r"(saddr), "l"(gptr));
}
#define CP_COMMIT() asm volatile("cp.async.commit_group;")
#define CP_WAIT1()  asm volatile("cp.async.wait_group 1;")

// ---------------------------------------------------------------------------
// fp32 -> tf32 bit conversion pass
// ---------------------------------------------------------------------------
__global__ void conv_tf32(const float4* __restrict__ in,
                          uint4* __restrict__ out, int n4)
{
    int i = blockIdx.x * blockDim.x + threadIdx.x;
    if (i < n4) {
        float4 v = in[i];
        uint4 o;
        o.x = f2tf(v.x); o.y = f2tf(v.y); o.z = f2tf(v.z); o.w = f2tf(v.w);
        out[i] = o;
    }
}

// ---------------------------------------------------------------------------
// TF32 GEMM, pre-converted operands, cp.async double buffer.
// C = A[M,K] @ B[K,N] + bias.  128x128x32 tile, 256 thr, warp tile 64x32.
// OUT_TF32: store tf32 bits (uint32) instead of fp32.
// ---------------------------------------------------------------------------
#define APAD 36
#define BPAD 136

template <bool OUT_TF32>
__global__ void __launch_bounds__(256, 2) gemm_tf32p(
    const uint32_t* __restrict__ A, const uint32_t* __restrict__ B,
    const float* __restrict__ bias, void* __restrict__ Cv,
    int M, int N, int K)
{
    __shared__ uint32_t As[2][128 * APAD];
    __shared__ uint32_t Bs[2][32 * BPAD];

    const int tid = threadIdx.x;
    const int lane = tid & 31;
    const int w = tid >> 5;
    const int wm = w >> 2;
    const int wn = w & 3;
    const int bm = blockIdx.y * 128;
    const int bn = blockIdx.x * 128;

    float acc[4][4][4];
    #pragma unroll
    for (int mt = 0; mt < 4; mt++)
        #pragma unroll
        for (int nt = 0; nt < 4; nt++)
            #pragma unroll
            for (int i = 0; i < 4; i++) acc[mt][nt][i] = 0.f;

    auto stage = [&](int k0, int buf) {
        // A tile 128x32 : 1024 16B chunks
        #pragma unroll
        for (int p = 0; p < 4; p++) {
            int c = tid + p * 256;
            int r = c >> 3, k4 = (c & 7) * 4;
            uint32_t dst = (uint32_t)__cvta_generic_to_shared(&As[buf][r * APAD + k4]);
            cpa16(dst, A + (size_t)(bm + r) * K + k0 + k4);
        }
        // B tile 32x128 : 1024 16B chunks
        #pragma unroll
        for (int p = 0; p < 4; p++) {
            int c = tid + p * 256;
            int r = c >> 5, n4 = (c & 31) * 4;
            uint32_t dst = (uint32_t)__cvta_generic_to_shared(&Bs[buf][r * BPAD + n4]);
            cpa16(dst, B + (size_t)(k0 + r) * N + bn + n4);
        }
    };

    stage(0, 0);
    CP_COMMIT();

    const int niter = K / 32;
    for (int it = 0; it < niter; it++) {
        if (it + 1 < niter) stage((it + 1) * 32, (it + 1) & 1);
        CP_COMMIT();
        CP_WAIT1();
        __syncthreads();

        const uint32_t* as = As[it & 1];
        const uint32_t* bs = Bs[it & 1];

        #pragma unroll
        for (int ks = 0; ks < 4; ks++) {
            uint32_t af[4][4], bf[4][2];
            const int col = ks * 8 + (lane & 3);
            #pragma unroll
            for (int mt = 0; mt < 4; mt++) {
                int row = wm * 64 + mt * 16 + (lane >> 2);
                af[mt][0] = as[row * APAD + col];
                af[mt][1] = as[(row + 8) * APAD + col];
                af[mt][2] = as[row * APAD + col + 4];
                af[mt][3] = as[(row + 8) * APAD + col + 4];
            }
            #pragma unroll
            for (int nt = 0; nt < 4; nt++) {
                int n = wn * 32 + nt * 8 + (lane >> 2);
                bf[nt][0] = bs[col * BPAD + n];
                bf[nt][1] = bs[(col + 4) * BPAD + n];
            }
            #pragma unroll
            for (int mt = 0; mt < 4; mt++)
                #pragma unroll
                for (int nt = 0; nt < 4; nt++)
                    mma_tf32(acc[mt][nt], af[mt], bf[nt], acc[mt][nt]);
        }
        __syncthreads();
    }

    #pragma unroll
    for (int mt = 0; mt < 4; mt++) {
        int row = bm + wm * 64 + mt * 16 + (lane >> 2);
        #pragma unroll
        for (int nt = 0; nt < 4; nt++) {
            int col = bn + wn * 32 + nt * 8 + (lane & 3) * 2;
            float b0 = bias[col], b1 = bias[col + 1];
            if (OUT_TF32) {
                uint32_t* C = (uint32_t*)Cv;
                uint2 v0 = make_uint2(f2tf(acc[mt][nt][0] + b0), f2tf(acc[mt][nt][1] + b1));
                uint2 v1 = make_uint2(f2tf(acc[mt][nt][2] + b0), f2tf(acc[mt][nt][3] + b1));
                *(uint2*)(C + (size_t)row * N + col) = v0;
                *(uint2*)(C + (size_t)(row + 8) * N + col) = v1;
            } else {
                float* C = (float*)Cv;
                float2 v0 = make_float2(acc[mt][nt][0] + b0, acc[mt][nt][1] + b1);
                float2 v1 = make_float2(acc[mt][nt][2] + b0, acc[mt][nt][3] + b1);
                *(float2*)(C + (size_t)row * N + col) = v0;
                *(float2*)(C + (size_t)(row + 8) * N + col) = v1;
            }
        }
    }
}

// ---------------------------------------------------------------------------
// Flash attention, tf32 mma, cp.async double-buffered K/V (raw tf32 copies).
// Block = (head, 128-query tile), 256 threads (8 warps x 16 q-rows).
// Ks[2][64][68] key-major; Vs[2][64][72] key-major; Ps[128][68].
// ---------------------------------------------------------------------------
#define PADK 68
#define PADV 72
#define QTILE 128
#define KS_OFF(b) ((b) * 64 * PADK)
#define VS_OFF(b) (2 * 64 * PADK + (b) * 64 * PADV)
#define PS_OFF    (2 * 64 * PADK + 2 * 64 * PADV)
#define AT_SMEM ((2 * 64 * PADK + 2 * 64 * PADV + QTILE * PADK) * 4)

__global__ void __launch_bounds__(256, 2) attn_tf32(
    const uint32_t* __restrict__ qkv, uint32_t* __restrict__ outt)
{
    extern __shared__ uint32_t sm_[];
    uint32_t* Ps = sm_ + PS_OFF;

    const int tid = threadIdx.x;
    const int lane = tid & 31;
    const int w = tid >> 5;
    const int h = blockIdx.y;
    const int qt = gridDim.x - 1 - blockIdx.x;   // heavy tiles first
    const int q0 = qt * QTILE;

    const uint32_t* qb = qkv + h * HD;
    const uint32_t* kb = qkv + DM + h * HD;
    const uint32_t* vb = qkv + 2 * DM + h * HD;

    // Stage Q tile (128x64) into Ps, extract register fragments
    for (int idx = tid; idx < 2048; idx += 256) {
        int r = idx >> 4, c = (idx & 15) * 4;
        uint4 v = *(const uint4*)(qb + (size_t)(q0 + r) * D3 + c);
        Ps[r * PADK + c + 0] = v.x;
        Ps[r * PADK + c + 1] = v.y;
        Ps[r * PADK + c + 2] = v.z;
        Ps[r * PADK + c + 3] = v.w;
    }
    __syncthreads();

    const int qrl = w * 16 + (lane >> 2);
    uint32_t qa[8][4];
    #pragma unroll
    for (int ks = 0; ks < 8; ks++) {
        int col = ks * 8 + (lane & 3);
        qa[ks][0] = Ps[qrl * PADK + col];
        qa[ks][1] = Ps[(qrl + 8) * PADK + col];
        qa[ks][2] = Ps[qrl * PADK + col + 4];
        qa[ks][3] = Ps[(qrl + 8) * PADK + col + 4];
    }
    __syncthreads();

    auto stage_kv = [&](int kt, int buf) {
        #pragma unroll
        for (int p = 0; p < 4; p++) {
            int c = tid + p * 256;
            int r = c >> 4, col = (c & 15) * 4;
            size_t grow = (size_t)(kt * 64 + r) * D3 + col;
            uint32_t dk = (uint32_t)__cvta_generic_to_shared(&sm_[KS_OFF(buf) + r * PADK + col]);
            cpa16(dk, kb + grow);
            uint32_t dv = (uint32_t)__cvta_generic_to_shared(&sm_[VS_OFF(buf) + r * PADV + col]);
            cpa16(dv, vb + grow);
        }
    };

    const int nkt = 2 * qt + 2;
    stage_kv(0, 0);
    CP_COMMIT();

    float m0 = -1e30f, m1 = -1e30f, l0 = 0.f, l1 = 0.f;
    float o[8][4];
    #pragma unroll
    for (int nt = 0; nt < 8; nt++)
        #pragma unroll
        for (int i = 0; i < 4; i++) o[nt][i] = 0.f;

    const float scale = 0.125f;
    const int gr0 = q0 + qrl;
    const int gr1 = gr0 + 8;

    for (int kt = 0; kt < nkt; kt++) {
        if (kt + 1 < nkt) stage_kv(kt + 1, (kt + 1) & 1);
        CP_COMMIT();
        CP_WAIT1();
        __syncthreads();

        const uint32_t* Ks = sm_ + KS_OFF(kt & 1);
        const uint32_t* Vs = sm_ + VS_OFF(kt & 1);

        // S = Q @ K^T
        float s[8][4];
        #pragma unroll
        for (int nt = 0; nt < 8; nt++)
            #pragma unroll
            for (int i = 0; i < 4; i++) s[nt][i] = 0.f;

        #pragma unroll
        for (int ks = 0; ks < 8; ks++) {
            const int d = ks * 8 + (lane & 3);
            #pragma unroll
            for (int nt = 0; nt < 8; nt++) {
                uint32_t bf[2];
                int key = nt * 8 + (lane >> 2);
                bf[0] = Ks[key * PADK + d];
                bf[1] = Ks[key * PADK + d + 4];
                mma_tf32(s[nt], qa[ks], bf, s[nt]);
            }
        }

        // Scale + causal mask (only tiles at/after the diagonal band)
        #pragma unroll
        for (int nt = 0; nt < 8; nt++) {
            #pragma unroll
            for (int i = 0; i < 4; i++) s[nt][i] *= scale;
        }
        if (kt >= 2 * qt) {
            #pragma unroll
            for (int nt = 0; nt < 8; nt++) {
                int colg = kt * 64 + nt * 8 + (lane & 3) * 2;
                if (colg > gr0) s[nt][0] = -1e30f;
                if (colg + 1 > gr0) s[nt][1] = -1e30f;
                if (colg > gr1) s[nt][2] = -1e30f;
                if (colg + 1 > gr1) s[nt][3] = -1e30f;
            }
        }

        // Online softmax (row stats across the 4-lane quad)
        float mx0 = -1e30f, mx1 = -1e30f;
        #pragma unroll
        for (int nt = 0; nt < 8; nt++) {
            mx0 = fmaxf(mx0, fmaxf(s[nt][0], s[nt][1]));
            mx1 = fmaxf(mx1, fmaxf(s[nt][2], s[nt][3]));
        }
        mx0 = fmaxf(mx0, __shfl_xor_sync(0xffffffffu, mx0, 1));
        mx0 = fmaxf(mx0, __shfl_xor_sync(0xffffffffu, mx0, 2));
        mx1 = fmaxf(mx1, __shfl_xor_sync(0xffffffffu, mx1, 1));
        mx1 = fmaxf(mx1, __shfl_xor_sync(0xffffffffu, mx1, 2));

        float nm0 = fmaxf(m0, mx0), nm1 = fmaxf(m1, mx1);
        float al0 = __expf(m0 - nm0), al1 = __expf(m1 - nm1);
        float sum0 = 0.f, sum1 = 0.f;

        #pragma unroll
        for (int nt = 0; nt < 8; nt++) {
            int kc = nt * 8 + (lane & 3) * 2;
            float p00 = __expf(s[nt][0] - nm0);
            float p01 = __expf(s[nt][1] - nm0);
            float p10 = __expf(s[nt][2] - nm1);
            float p11 = __expf(s[nt][3] - nm1);
            sum0 += p00 + p01;
            sum1 += p10 + p11;
            Ps[qrl * PADK + kc] = f2tf(p00);
            Ps[qrl * PADK + kc + 1] = f2tf(p01);
            Ps[(qrl + 8) * PADK + kc] = f2tf(p10);
            Ps[(qrl + 8) * PADK + kc + 1] = f2tf(p11);
        }
        sum0 += __shfl_xor_sync(0xffffffffu, sum0, 1);
        sum0 += __shfl_xor_sync(0xffffffffu, sum0, 2);
        sum1 += __shfl_xor_sync(0xffffffffu, sum1, 1);
        sum1 += __shfl_xor_sync(0xffffffffu, sum1, 2);

        l0 = l0 * al0 + sum0;
        l1 = l1 * al1 + sum1;
        m0 = nm0;
        m1 = nm1;
        #pragma unroll
        for (int nt = 0; nt < 8; nt++) {
            o[nt][0] *= al0;
            o[nt][1] *= al0;
            o[nt][2] *= al1;
            o[nt][3] *= al1;
        }
        __syncwarp();  // Ps rows are warp-private

        // O += P @ V (V row-major [key][d], PADV=72 -> conflict-free b-frags)
        #pragma unroll
        for (int ks = 0; ks < 8; ks++) {
            uint32_t af[4];
            int kc = ks * 8 + (lane & 3);
            af[0] = Ps[qrl * PADK + kc];
            af[1] = Ps[(qrl + 8) * PADK + kc];
            af[2] = Ps[qrl * PADK + kc + 4];
            af[3] = Ps[(qrl + 8) * PADK + kc + 4];
            #pragma unroll
            for (int nt = 0; nt < 8; nt++) {
                uint32_t bf[2];
                int d = nt * 8 + (lane >> 2);
                bf[0] = Vs[(ks * 8 + (lane & 3)) * PADV + d];
                bf[1] = Vs[(ks * 8 + (lane & 3) + 4) * PADV + d];
                mma_tf32(o[nt], af, bf, o[nt]);
            }
        }
        __syncthreads();
    }

    // Epilogue: write tf32 bits for the output projection's A operand
    float inv0 = 1.f / l0, inv1 = 1.f / l1;
    #pragma unroll
    for (int nt = 0; nt < 8; nt++) {
        int col = h * HD + nt * 8 + (lane & 3) * 2;
        uint2 v0 = make_uint2(f2tf(o[nt][0] * inv0), f2tf(o[nt][1] * inv0));
        uint2 v1 = make_uint2(f2tf(o[nt][2] * inv1), f2tf(o[nt][3] * inv1));
        *(uint2*)(outt + (size_t)(q0 + qrl) * DM + col) = v0;
        *(uint2*)(outt + (size_t)(q0 + qrl + 8) * DM + col) = v1;
    }
}

// ---------------------------------------------------------------------------
// Launch
// ---------------------------------------------------------------------------
extern "C" void kernel_launch(void* const* d_in, const int* in_sizes, int n_in,
                              void* d_out, int out_size)
{
    const float* x    = (const float*)d_in[0];
    const float* Wqkv = (const float*)d_in[1];
    const float* bqkv = (const float*)d_in[2];
    const float* Wout = (const float*)d_in[3];
    const float* bout = (const float*)d_in[4];
    float* out = (float*)d_out;

    uint32_t *xt, *wqkvt, *woutt, *qkv, *attn;
    cudaGetSymbolAddress((void**)&xt,    g_xt);
    cudaGetSymbolAddress((void**)&wqkvt, g_wqkvt);
    cudaGetSymbolAddress((void**)&woutt, g_woutt);
    cudaGetSymbolAddress((void**)&qkv,   g_qkv);
    cudaGetSymbolAddress((void**)&attn,  g_attn);

    // 0) pre-convert fp32 -> tf32 bits
    {
        int n4;
        n4 = SQ * DM / 4;
        conv_tf32<<<(n4 + 255) / 256, 256>>>((const float4*)x, (uint4*)xt, n4);
        n4 = DM * D3 / 4;
        conv_tf32<<<(n4 + 255) / 256, 256>>>((const float4*)Wqkv, (uint4*)wqkvt, n4);
        n4 = DM * DM / 4;
        conv_tf32<<<(n4 + 255) / 256, 256>>>((const float4*)Wout, (uint4*)woutt, n4);
    }

    // 1) QKV projection -> tf32 bits
    {
        dim3 grid(D3 / 128, SQ / 128);
        gemm_tf32p<true><<<grid, 256>>>(xt, wqkvt, bqkv, qkv, SQ, D3, DM);
    }

    // 2) Flash attention -> tf32 bits
    {
        cudaFuncSetAttribute(attn_tf32,
                             cudaFuncAttributeMaxDynamicSharedMemorySize,
                             AT_SMEM);
        dim3 grid(SQ / QTILE, NH);
        attn_tf32<<<grid, 256, AT_SMEM>>>(qkv, attn);
    }

    // 3) Output projection -> fp32
    {
        dim3 grid(DM / 128, SQ / 128);
        gemm_tf32p<false><<<grid, 256>>>(attn, woutt, bout, out, SQ, DM, DM);
    }
}

// round 4
// speedup vs baseline: 7.7023x; 2.1057x over previous
#include <cuda_runtime.h>
#include <cuda_fp16.h>
#include <cstdint>

#define SQ 4096
#define DM 1024
#define NH 16
#define HD 64
#define D3 3072

// fp16 scratch (allocation-free -> device globals)
__device__ __half g_xh[SQ * DM];
__device__ __half g_wqkvh[DM * D3];
__device__ __half g_wouth[DM * DM];
__device__ __half g_qkv[SQ * D3];
__device__ __half g_attn[SQ * DM];

// ---------------------------------------------------------------------------
// helpers
// ---------------------------------------------------------------------------
__device__ __forceinline__ void ldsm4(uint32_t* r, uint32_t a) {
    asm volatile("ldmatrix.sync.aligned.m8n8.x4.shared.b16 {%0,%1,%2,%3}, [%4];"
                 : "=r"(r[0]), "=r"(r[1]), "=r"(r[2]), "=r"(r[3]) : "r"(a));
}
__device__ __forceinline__ void ldsm4t(uint32_t* r, uint32_t a) {
    asm volatile("ldmatrix.sync.aligned.m8n8.x4.trans.shared.b16 {%0,%1,%2,%3}, [%4];"
                 : "=r"(r[0]), "=r"(r[1]), "=r"(r[2]), "=r"(r[3]) : "r"(a));
}
__device__ __forceinline__ void mma16(float* d, const uint32_t* a,
                                      const uint32_t* b, const float* c) {
    asm volatile(
        "mma.sync.aligned.m16n8k16.row.col.f32.f16.f16.f32 "
        "{%0,%1,%2,%3}, {%4,%5,%6,%7}, {%8,%9}, {%10,%11,%12,%13};"
        : "=f"(d[0]), "=f"(d[1]), "=f"(d[2]), "=f"(d[3])
        : "r"(a[0]), "r"(a[1]), "r"(a[2]), "r"(a[3]),
          "r"(b[0]), "r"(b[1]),
          "f"(c[0]), "f"(c[1]), "f"(c[2]), "f"(c[3]));
}
__device__ __forceinline__ void cpa16(uint32_t saddr, const void* gptr) {
    asm volatile("cp.async.cg.shared.global [%0], [%1], 16;"
                 :: "r"(saddr), "l"(gptr));
}
#define CP_COMMIT() asm volatile("cp.async.commit_group;")
#define CP_WAIT(n)  asm volatile("cp.async.wait_group %0;" :: "n"(n))

__device__ __forceinline__ uint32_t h2u(__half2 h) {
    return *reinterpret_cast<uint32_t*>(&h);
}
__device__ __forceinline__ uint32_t sm_u32(const void* p) {
    return (uint32_t)__cvta_generic_to_shared(p);
}

// fp32 -> fp16 conversion
__global__ void conv_h(const float4* __restrict__ in,
                       __half2* __restrict__ out, int n4)
{
    int i = blockIdx.x * blockDim.x + threadIdx.x;
    if (i < n4) {
        float4 v = in[i];
        out[2 * i]     = __floats2half2_rn(v.x, v.y);
        out[2 * i + 1] = __floats2half2_rn(v.z, v.w);
    }
}

// ---------------------------------------------------------------------------
// FP16 GEMM: C = A[M,K] @ B[K,N] + bias. 128x128x32 tile, 256 thr,
// warp tile 64x32, 3-stage cp.async ring, ldmatrix fragments.
// OUT_HALF: write __half, else fp32.
// ---------------------------------------------------------------------------
#define SA 40     // As row stride (halves): 20 words -> LDSM conflict-free
#define SB 136    // Bs row stride: 68 words == 4 mod 32 -> conflict-free
#define GSTAGE_H (128 * SA + 32 * SB)   // halves per stage
#define G_SMEM (3 * GSTAGE_H * 2)

template <bool OUT_HALF>
__global__ void __launch_bounds__(256, 2) gemm_h(
    const __half* __restrict__ A, const __half* __restrict__ B,
    const float* __restrict__ bias, void* __restrict__ Cv,
    int M, int N, int K)
{
    extern __shared__ __half smg[];

    const int tid = threadIdx.x;
    const int lane = tid & 31;
    const int w = tid >> 5;
    const int wm = w >> 2;
    const int wn = w & 3;
    const int bm = blockIdx.y * 128;
    const int bn = blockIdx.x * 128;
    const int sub = lane >> 3;
    const int lr = lane & 7;

    float acc[4][4][4];
    #pragma unroll
    for (int mt = 0; mt < 4; mt++)
        #pragma unroll
        for (int nt = 0; nt < 4; nt++)
            #pragma unroll
            for (int i = 0; i < 4; i++) acc[mt][nt][i] = 0.f;

    auto stage = [&](int k0, int s) {
        __half* As = smg + s * GSTAGE_H;
        __half* Bs = As + 128 * SA;
        #pragma unroll
        for (int p = 0; p < 2; p++) {          // A: 128x32 halves, 512 chunks
            int c = tid + p * 256;
            int r = c >> 2, col = (c & 3) * 8;
            cpa16(sm_u32(As + r * SA + col), A + (size_t)(bm + r) * K + k0 + col);
        }
        #pragma unroll
        for (int p = 0; p < 2; p++) {          // B: 32x128 halves, 512 chunks
            int c = tid + p * 256;
            int r = c >> 4, col = (c & 15) * 8;
            cpa16(sm_u32(Bs + r * SB + col), B + (size_t)(k0 + r) * N + bn + col);
        }
    };

    const int niter = K / 32;
    stage(0, 0); CP_COMMIT();
    stage(32, 1); CP_COMMIT();

    for (int it = 0; it < niter; it++) {
        CP_WAIT(1);
        __syncthreads();
        if (it + 2 < niter) stage((it + 2) * 32, (it + 2) % 3);
        CP_COMMIT();

        const __half* As = smg + (it % 3) * GSTAGE_H;
        const __half* Bs = As + 128 * SA;

        #pragma unroll
        for (int ks = 0; ks < 2; ks++) {
            const int k0 = ks * 16;
            uint32_t af[4][4], bf[4][2];
            #pragma unroll
            for (int mt = 0; mt < 4; mt++) {
                int row = wm * 64 + mt * 16 + (sub & 1) * 8 + lr;
                ldsm4(af[mt], sm_u32(As + row * SA + k0 + (sub >> 1) * 8));
            }
            #pragma unroll
            for (int ntp = 0; ntp < 2; ntp++) {
                int n0 = wn * 32 + ntp * 16;
                uint32_t r4[4];
                ldsm4t(r4, sm_u32(Bs + (k0 + (sub & 1) * 8 + lr) * SB
                                     + n0 + (sub >> 1) * 8));
                bf[ntp * 2][0] = r4[0]; bf[ntp * 2][1] = r4[1];
                bf[ntp * 2 + 1][0] = r4[2]; bf[ntp * 2 + 1][1] = r4[3];
            }
            #pragma unroll
            for (int mt = 0; mt < 4; mt++)
                #pragma unroll
                for (int nt = 0; nt < 4; nt++)
                    mma16(acc[mt][nt], af[mt], bf[nt], acc[mt][nt]);
        }
        __syncthreads();
    }

    #pragma unroll
    for (int mt = 0; mt < 4; mt++) {
        int row = bm + wm * 64 + mt * 16 + (lane >> 2);
        #pragma unroll
        for (int nt = 0; nt < 4; nt++) {
            int col = bn + wn * 32 + nt * 8 + (lane & 3) * 2;
            float b0 = bias[col], b1 = bias[col + 1];
            if (OUT_HALF) {
                __half* C = (__half*)Cv;
                *(__half2*)(C + (size_t)row * N + col) =
                    __floats2half2_rn(acc[mt][nt][0] + b0, acc[mt][nt][1] + b1);
                *(__half2*)(C + (size_t)(row + 8) * N + col) =
                    __floats2half2_rn(acc[mt][nt][2] + b0, acc[mt][nt][3] + b1);
            } else {
                float* C = (float*)Cv;
                *(float2*)(C + (size_t)row * N + col) =
                    make_float2(acc[mt][nt][0] + b0, acc[mt][nt][1] + b1);
                *(float2*)(C + (size_t)(row + 8) * N + col) =
                    make_float2(acc[mt][nt][2] + b0, acc[mt][nt][3] + b1);
            }
        }
    }
}

// ---------------------------------------------------------------------------
// Flash attention, fp16 mma m16n8k16, P register-resident.
// Block = (head, 128-q tile), 256 threads; warp w owns q rows [16w,16w+16).
// 3-stage K/V ring in dynamic smem; Q staged through stage-0 region.
// ---------------------------------------------------------------------------
#define SK 72                         // K/V row stride (halves), 36 words
#define KV_H (64 * SK)                // one K or V tile, halves
#define ASTAGE_H (2 * KV_H)           // K+V per stage
#define AT_SMEM (3 * ASTAGE_H * 2)

__global__ void __launch_bounds__(256, 2) attn_h(
    const __half* __restrict__ qkv, __half* __restrict__ outh)
{
    extern __shared__ __half sma[];

    const int tid = threadIdx.x;
    const int lane = tid & 31;
    const int w = tid >> 5;
    const int sub = lane >> 3;
    const int lr = lane & 7;
    const int h = blockIdx.y;
    const int qt = gridDim.x - 1 - blockIdx.x;  // heavy tiles first
    const int q0 = qt * 128;

    const __half* qb = qkv + h * HD;
    const __half* kb = qkv + DM + h * HD;
    const __half* vb = qkv + 2 * DM + h * HD;

    // --- Stage Q (128x64) into sm[0..9216), extract register a-frags ---
    for (int p = 0; p < 4; p++) {
        int c = tid + p * 256;
        int r = c >> 3, col = (c & 7) * 8;
        cpa16(sm_u32(sma + r * SK + col), qb + (size_t)(q0 + r) * D3 + col);
    }
    CP_COMMIT(); CP_WAIT(0);
    __syncthreads();

    uint32_t qa[4][4];
    #pragma unroll
    for (int kq = 0; kq < 4; kq++) {
        int row = w * 16 + (sub & 1) * 8 + lr;
        ldsm4(qa[kq], sm_u32(sma + row * SK + kq * 16 + (sub >> 1) * 8));
    }
    __syncthreads();   // Q frags extracted; smem free for K/V ring

    auto stage_kv = [&](int kt, int s) {
        __half* Ks = sma + s * ASTAGE_H;
        __half* Vs = Ks + KV_H;
        #pragma unroll
        for (int p = 0; p < 2; p++) {
            int c = tid + p * 256;
            int r = c >> 3, col = (c & 7) * 8;
            size_t g = (size_t)(kt * 64 + r) * D3 + col;
            cpa16(sm_u32(Ks + r * SK + col), kb + g);
            cpa16(sm_u32(Vs + r * SK + col), vb + g);
        }
    };

    const int nkt = 2 * qt + 2;
    stage_kv(0, 0); CP_COMMIT();
    if (nkt > 1) stage_kv(1, 1);
    CP_COMMIT();

    float m0 = -1e30f, m1 = -1e30f, l0 = 0.f, l1 = 0.f;
    float o[8][4];
    #pragma unroll
    for (int nt = 0; nt < 8; nt++)
        #pragma unroll
        for (int i = 0; i < 4; i++) o[nt][i] = 0.f;

    const float sc = 0.125f * 1.44269504088896f;  // scale * log2(e)
    const int gr0 = q0 + w * 16 + (lane >> 2);
    const int gr1 = gr0 + 8;

    for (int kt = 0; kt < nkt; kt++) {
        CP_WAIT(1);
        __syncthreads();
        if (kt + 2 < nkt) stage_kv(kt + 2, (kt + 2) % 3);
        CP_COMMIT();

        const __half* Ks = sma + (kt % 3) * ASTAGE_H;
        const __half* Vs = Ks + KV_H;

        // ---- S = Q @ K^T : 8 key-tiles of 8, k over d=64 (4 steps) ----
        float s[8][4];
        #pragma unroll
        for (int nt = 0; nt < 8; nt++)
            #pragma unroll
            for (int i = 0; i < 4; i++) s[nt][i] = 0.f;

        #pragma unroll
        for (int kq = 0; kq < 4; kq++) {
            const int k0 = kq * 16;
            #pragma unroll
            for (int ntp = 0; ntp < 4; ntp++) {
                const int n0 = ntp * 16;   // key offset
                uint32_t r4[4];
                ldsm4(r4, sm_u32(Ks + (n0 + (sub >> 1) * 8 + lr) * SK
                                    + k0 + (sub & 1) * 8));
                uint32_t b0[2] = {r4[0], r4[1]};
                uint32_t b1[2] = {r4[2], r4[3]};
                mma16(s[ntp * 2], qa[kq], b0, s[ntp * 2]);
                mma16(s[ntp * 2 + 1], qa[kq], b1, s[ntp * 2 + 1]);
            }
        }

        // ---- scale (log2 domain) + causal mask on diagonal band ----
        #pragma unroll
        for (int nt = 0; nt < 8; nt++)
            #pragma unroll
            for (int i = 0; i < 4; i++) s[nt][i] *= sc;
        if (kt >= 2 * qt) {
            #pragma unroll
            for (int nt = 0; nt < 8; nt++) {
                int colg = kt * 64 + nt * 8 + (lane & 3) * 2;
                if (colg > gr0) s[nt][0] = -1e30f;
                if (colg + 1 > gr0) s[nt][1] = -1e30f;
                if (colg > gr1) s[nt][2] = -1e30f;
                if (colg + 1 > gr1) s[nt][3] = -1e30f;
            }
        }

        // ---- online softmax (rows across the 4-lane quad) ----
        float mx0 = -1e30f, mx1 = -1e30f;
        #pragma unroll
        for (int nt = 0; nt < 8; nt++) {
            mx0 = fmaxf(mx0, fmaxf(s[nt][0], s[nt][1]));
            mx1 = fmaxf(mx1, fmaxf(s[nt][2], s[nt][3]));
        }
        mx0 = fmaxf(mx0, __shfl_xor_sync(0xffffffffu, mx0, 1));
        mx0 = fmaxf(mx0, __shfl_xor_sync(0xffffffffu, mx0, 2));
        mx1 = fmaxf(mx1, __shfl_xor_sync(0xffffffffu, mx1, 1));
        mx1 = fmaxf(mx1, __shfl_xor_sync(0xffffffffu, mx1, 2));

        float nm0 = fmaxf(m0, mx0), nm1 = fmaxf(m1, mx1);
        float al0 = exp2f(m0 - nm0), al1 = exp2f(m1 - nm1);
        float sum0 = 0.f, sum1 = 0.f;
        uint32_t pa[8][2];    // P packed half2, mma A-frag layout

        #pragma unroll
        for (int nt = 0; nt < 8; nt++) {
            float p00 = exp2f(s[nt][0] - nm0);
            float p01 = exp2f(s[nt][1] - nm0);
            float p10 = exp2f(s[nt][2] - nm1);
            float p11 = exp2f(s[nt][3] - nm1);
            sum0 += p00 + p01;
            sum1 += p10 + p11;
            pa[nt][0] = h2u(__floats2half2_rn(p00, p01));
            pa[nt][1] = h2u(__floats2half2_rn(p10, p11));
        }
        sum0 += __shfl_xor_sync(0xffffffffu, sum0, 1);
        sum0 += __shfl_xor_sync(0xffffffffu, sum0, 2);
        sum1 += __shfl_xor_sync(0xffffffffu, sum1, 1);
        sum1 += __shfl_xor_sync(0xffffffffu, sum1, 2);

        l0 = l0 * al0 + sum0;
        l1 = l1 * al1 + sum1;
        m0 = nm0; m1 = nm1;
        #pragma unroll
        for (int nt = 0; nt < 8; nt++) {
            o[nt][0] *= al0; o[nt][1] *= al0;
            o[nt][2] *= al1; o[nt][3] *= al1;
        }

        // ---- O += P @ V : P in registers, V b-frags via ldmatrix.trans ----
        #pragma unroll
        for (int kp = 0; kp < 4; kp++) {      // 16 keys per step
            uint32_t af[4] = {pa[2 * kp][0], pa[2 * kp][1],
                              pa[2 * kp + 1][0], pa[2 * kp + 1][1]};
            #pragma unroll
            for (int ntp = 0; ntp < 4; ntp++) {   // 16 d per ldsm
                const int n0 = ntp * 16;
                uint32_t r4[4];
                ldsm4t(r4, sm_u32(Vs + (kp * 16 + (sub & 1) * 8 + lr) * SK
                                     + n0 + (sub >> 1) * 8));
                uint32_t b0[2] = {r4[0], r4[1]};
                uint32_t b1[2] = {r4[2], r4[3]};
                mma16(o[ntp * 2], af, b0, o[ntp * 2]);
                mma16(o[ntp * 2 + 1], af, b1, o[ntp * 2 + 1]);
            }
        }
        __syncthreads();
    }

    // ---- epilogue: out[q, h*64+d] = o / l, as fp16 ----
    float inv0 = 1.f / l0, inv1 = 1.f / l1;
    const int qrl = w * 16 + (lane >> 2);
    #pragma unroll
    for (int nt = 0; nt < 8; nt++) {
        int col = h * HD + nt * 8 + (lane & 3) * 2;
        *(__half2*)(outh + (size_t)(q0 + qrl) * DM + col) =
            __floats2half2_rn(o[nt][0] * inv0, o[nt][1] * inv0);
        *(__half2*)(outh + (size_t)(q0 + qrl + 8) * DM + col) =
            __floats2half2_rn(o[nt][2] * inv1, o[nt][3] * inv1);
    }
}

// ---------------------------------------------------------------------------
// Launch
// ---------------------------------------------------------------------------
extern "C" void kernel_launch(void* const* d_in, const int* in_sizes, int n_in,
                              void* d_out, int out_size)
{
    const float* x    = (const float*)d_in[0];
    const float* Wqkv = (const float*)d_in[1];
    const float* bqkv = (const float*)d_in[2];
    const float* Wout = (const float*)d_in[3];
    const float* bout = (const float*)d_in[4];
    float* out = (float*)d_out;

    __half *xh, *wqkvh, *wouth, *qkv, *attn;
    cudaGetSymbolAddress((void**)&xh,    g_xh);
    cudaGetSymbolAddress((void**)&wqkvh, g_wqkvh);
    cudaGetSymbolAddress((void**)&wouth, g_wouth);
    cudaGetSymbolAddress((void**)&qkv,   g_qkv);
    cudaGetSymbolAddress((void**)&attn,  g_attn);

    // 0) fp32 -> fp16
    {
        int n4;
        n4 = SQ * DM / 4;
        conv_h<<<(n4 + 255) / 256, 256>>>((const float4*)x, (__half2*)xh, n4);
        n4 = DM * D3 / 4;
        conv_h<<<(n4 + 255) / 256, 256>>>((const float4*)Wqkv, (__half2*)wqkvh, n4);
        n4 = DM * DM / 4;
        conv_h<<<(n4 + 255) / 256, 256>>>((const float4*)Wout, (__half2*)wouth, n4);
    }

    // 1) QKV projection -> fp16
    {
        cudaFuncSetAttribute(gemm_h<true>,
                             cudaFuncAttributeMaxDynamicSharedMemorySize, G_SMEM);
        dim3 grid(D3 / 128, SQ / 128);
        gemm_h<true><<<grid, 256, G_SMEM>>>(xh, wqkvh, bqkv, qkv, SQ, D3, DM);
    }

    // 2) Flash attention -> fp16
    {
        cudaFuncSetAttribute(attn_h,
                             cudaFuncAttributeMaxDynamicSharedMemorySize, AT_SMEM);
        dim3 grid(SQ / 128, NH);
        attn_h<<<grid, 256, AT_SMEM>>>(qkv, attn);
    }

    // 3) Output projection -> fp32
    {
        cudaFuncSetAttribute(gemm_h<false>,
                             cudaFuncAttributeMaxDynamicSharedMemorySize, G_SMEM);
        dim3 grid(DM / 128, SQ / 128);
        gemm_h<false><<<grid, 256, G_SMEM>>>(attn, wouth, bout, out, SQ, DM, DM);
    }
}

// round 6
// speedup vs baseline: 8.5222x; 1.1064x over previous
#include <cuda_runtime.h>
#include <cuda_fp16.h>
#include <cstdint>

#define SQ 4096
#define DM 1024
#define NH 16
#define HD 64
#define D3 3072

// fp16 scratch (allocation-free -> device globals)
__device__ __half g_xh[SQ * DM];
__device__ __half g_wqkvh[DM * D3];
__device__ __half g_wouth[DM * DM];
__device__ __half g_qkv[SQ * D3];
__device__ __half g_attn[SQ * DM];

// ---------------------------------------------------------------------------
// helpers
// ---------------------------------------------------------------------------
__device__ __forceinline__ void ldsm4(uint32_t* r, uint32_t a) {
    asm volatile("ldmatrix.sync.aligned.m8n8.x4.shared.b16 {%0,%1,%2,%3}, [%4];"
                 : "=r"(r[0]), "=r"(r[1]), "=r"(r[2]), "=r"(r[3]) : "r"(a));
}
__device__ __forceinline__ void ldsm4t(uint32_t* r, uint32_t a) {
    asm volatile("ldmatrix.sync.aligned.m8n8.x4.trans.shared.b16 {%0,%1,%2,%3}, [%4];"
                 : "=r"(r[0]), "=r"(r[1]), "=r"(r[2]), "=r"(r[3]) : "r"(a));
}
__device__ __forceinline__ void mma16(float* d, const uint32_t* a,
                                      const uint32_t* b, const float* c) {
    asm volatile(
        "mma.sync.aligned.m16n8k16.row.col.f32.f16.f16.f32 "
        "{%0,%1,%2,%3}, {%4,%5,%6,%7}, {%8,%9}, {%10,%11,%12,%13};"
        : "=f"(d[0]), "=f"(d[1]), "=f"(d[2]), "=f"(d[3])
        : "r"(a[0]), "r"(a[1]), "r"(a[2]), "r"(a[3]),
          "r"(b[0]), "r"(b[1]),
          "f"(c[0]), "f"(c[1]), "f"(c[2]), "f"(c[3]));
}
__device__ __forceinline__ void cpa16(uint32_t saddr, const void* gptr) {
    asm volatile("cp.async.cg.shared.global [%0], [%1], 16;"
                 :: "r"(saddr), "l"(gptr));
}
#define CP_COMMIT() asm volatile("cp.async.commit_group;")
#define CP_WAIT(n)  asm volatile("cp.async.wait_group %0;" :: "n"(n))

__device__ __forceinline__ uint32_t h2u(__half2 h) {
    return *reinterpret_cast<uint32_t*>(&h);
}
__device__ __forceinline__ uint32_t sm_u32(const void* p) {
    return (uint32_t)__cvta_generic_to_shared(p);
}

// fp32 -> fp16 conversion
__global__ void conv_h(const float4* __restrict__ in,
                       __half2* __restrict__ out, int n4)
{
    int i = blockIdx.x * blockDim.x + threadIdx.x;
    if (i < n4) {
        float4 v = in[i];
        out[2 * i]     = __floats2half2_rn(v.x, v.y);
        out[2 * i + 1] = __floats2half2_rn(v.z, v.w);
    }
}

// ---------------------------------------------------------------------------
// FP16 GEMM: C = A[M,K] @ B[K,N] + bias. 128x128x64 tile, 256 thr,
// warp tile 64x32, 3-stage cp.async ring (K=64 per stage), ldmatrix frags.
// ---------------------------------------------------------------------------
#define SA 72     // As row stride (halves): 144B, 16B-offset rows -> LDSM clean
#define SB 136    // Bs row stride (halves): 272B -> LDSM clean
#define GSTAGE_H (128 * SA + 64 * SB)    // halves per stage (35840B)
#define G_SMEM (3 * GSTAGE_H * 2)

template <bool OUT_HALF>
__global__ void __launch_bounds__(256, 2) gemm_h(
    const __half* __restrict__ A, const __half* __restrict__ B,
    const float* __restrict__ bias, void* __restrict__ Cv,
    int M, int N, int K)
{
    extern __shared__ __half smg[];

    const int tid = threadIdx.x;
    const int lane = tid & 31;
    const int w = tid >> 5;
    const int wm = w >> 2;
    const int wn = w & 3;
    const int bm = blockIdx.y * 128;
    const int bn = blockIdx.x * 128;
    const int sub = lane >> 3;
    const int lr = lane & 7;

    float acc[4][4][4];
    #pragma unroll
    for (int mt = 0; mt < 4; mt++)
        #pragma unroll
        for (int nt = 0; nt < 4; nt++)
            #pragma unroll
            for (int i = 0; i < 4; i++) acc[mt][nt][i] = 0.f;

    auto stage = [&](int kb, int s) {
        __half* As = smg + s * GSTAGE_H;
        __half* Bs = As + 128 * SA;
        #pragma unroll
        for (int p = 0; p < 4; p++) {          // A: 128x64 halves, 1024 chunks
            int c = tid + p * 256;
            int r = c >> 3, col = (c & 7) * 8;
            cpa16(sm_u32(As + r * SA + col), A + (size_t)(bm + r) * K + kb * 64 + col);
        }
        #pragma unroll
        for (int p = 0; p < 4; p++) {          // B: 64x128 halves, 1024 chunks
            int c = tid + p * 256;
            int r = c >> 4, col = (c & 15) * 8;
            cpa16(sm_u32(Bs + r * SB + col), B + (size_t)(kb * 64 + r) * N + bn + col);
        }
    };

    const int niter = K / 64;
    stage(0, 0); CP_COMMIT();
    stage(1, 1); CP_COMMIT();

    for (int it = 0; it < niter; it++) {
        CP_WAIT(1);
        __syncthreads();
        if (it + 2 < niter) stage(it + 2, (it + 2) % 3);
        CP_COMMIT();

        const __half* As = smg + (it % 3) * GSTAGE_H;
        const __half* Bs = As + 128 * SA;

        #pragma unroll
        for (int ks = 0; ks < 4; ks++) {
            const int k0 = ks * 16;
            uint32_t af[4][4], bf[4][2];
            #pragma unroll
            for (int mt = 0; mt < 4; mt++) {
                int row = wm * 64 + mt * 16 + (sub & 1) * 8 + lr;
                ldsm4(af[mt], sm_u32(As + row * SA + k0 + (sub >> 1) * 8));
            }
            #pragma unroll
            for (int ntp = 0; ntp < 2; ntp++) {
                int n0 = wn * 32 + ntp * 16;
                uint32_t r4[4];
                ldsm4t(r4, sm_u32(Bs + (k0 + (sub & 1) * 8 + lr) * SB
                                     + n0 + (sub >> 1) * 8));
                bf[ntp * 2][0] = r4[0]; bf[ntp * 2][1] = r4[1];
                bf[ntp * 2 + 1][0] = r4[2]; bf[ntp * 2 + 1][1] = r4[3];
            }
            #pragma unroll
            for (int mt = 0; mt < 4; mt++)
                #pragma unroll
                for (int nt = 0; nt < 4; nt++)
                    mma16(acc[mt][nt], af[mt], bf[nt], acc[mt][nt]);
        }
        __syncthreads();
    }

    #pragma unroll
    for (int mt = 0; mt < 4; mt++) {
        int row = bm + wm * 64 + mt * 16 + (lane >> 2);
        #pragma unroll
        for (int nt = 0; nt < 4; nt++) {
            int col = bn + wn * 32 + nt * 8 + (lane & 3) * 2;
            float b0 = bias[col], b1 = bias[col + 1];
            if (OUT_HALF) {
                __half* C = (__half*)Cv;
                *(__half2*)(C + (size_t)row * N + col) =
                    __floats2half2_rn(acc[mt][nt][0] + b0, acc[mt][nt][1] + b1);
                *(__half2*)(C + (size_t)(row + 8) * N + col) =
                    __floats2half2_rn(acc[mt][nt][2] + b0, acc[mt][nt][3] + b1);
            } else {
                float* C = (float*)Cv;
                *(float2*)(C + (size_t)row * N + col) =
                    make_float2(acc[mt][nt][0] + b0, acc[mt][nt][1] + b1);
                *(float2*)(C + (size_t)(row + 8) * N + col) =
                    make_float2(acc[mt][nt][2] + b0, acc[mt][nt][3] + b1);
            }
        }
    }
}

// ---------------------------------------------------------------------------
// Flash attention, fp16 mma m16n8k16, P register-resident.
// Grid (16, NH). Each CTA processes TWO q-tiles: qt = 31-bx (heavy) then
// qt = bx (light) -> every CTA does exactly 66 kt-iterations: one balanced
// wave of 256 CTAs over the 296 concurrent slots.
// ---------------------------------------------------------------------------
#define SK 72
#define KV_H (64 * SK)
#define ASTAGE_H (2 * KV_H)
#define AT_SMEM (3 * ASTAGE_H * 2)

__global__ void __launch_bounds__(256, 2) attn_h(
    const __half* __restrict__ qkv, __half* __restrict__ outh)
{
    extern __shared__ __half sma[];

    const int tid = threadIdx.x;
    const int lane = tid & 31;
    const int w = tid >> 5;
    const int sub = lane >> 3;
    const int lr = lane & 7;
    const int h = blockIdx.y;

    const __half* qb = qkv + h * HD;
    const __half* kb = qkv + DM + h * HD;
    const __half* vb = qkv + 2 * DM + h * HD;

    #pragma unroll 1
    for (int pass = 0; pass < 2; pass++) {
        const int qt = (pass == 0) ? (31 - (int)blockIdx.x) : (int)blockIdx.x;
        const int q0 = qt * 128;

        // --- Stage Q (128x64) into slot 0 region, extract register a-frags ---
        for (int p = 0; p < 4; p++) {
            int c = tid + p * 256;
            int r = c >> 3, col = (c & 7) * 8;
            cpa16(sm_u32(sma + r * SK + col), qb + (size_t)(q0 + r) * D3 + col);
        }
        CP_COMMIT(); CP_WAIT(0);
        __syncthreads();

        uint32_t qa[4][4];
        #pragma unroll
        for (int kq = 0; kq < 4; kq++) {
            int row = w * 16 + (sub & 1) * 8 + lr;
            ldsm4(qa[kq], sm_u32(sma + row * SK + kq * 16 + (sub >> 1) * 8));
        }
        __syncthreads();   // Q frags extracted; smem free for K/V ring

        auto stage_kv = [&](int kt, int s) {
            __half* Ks = sma + s * ASTAGE_H;
            __half* Vs = Ks + KV_H;
            #pragma unroll
            for (int p = 0; p < 2; p++) {
                int c = tid + p * 256;
                int r = c >> 3, col = (c & 7) * 8;
                size_t g = (size_t)(kt * 64 + r) * D3 + col;
                cpa16(sm_u32(Ks + r * SK + col), kb + g);
                cpa16(sm_u32(Vs + r * SK + col), vb + g);
            }
        };

        const int nkt = 2 * qt + 2;
        stage_kv(0, 0); CP_COMMIT();
        if (nkt > 1) stage_kv(1, 1);
        CP_COMMIT();

        float m0 = -1e30f, m1 = -1e30f, l0 = 0.f, l1 = 0.f;
        float o[8][4];
        #pragma unroll
        for (int nt = 0; nt < 8; nt++)
            #pragma unroll
            for (int i = 0; i < 4; i++) o[nt][i] = 0.f;

        const float sc = 0.125f * 1.44269504088896f;  // scale * log2(e)
        const int gr0 = q0 + w * 16 + (lane >> 2);
        const int gr1 = gr0 + 8;

        for (int kt = 0; kt < nkt; kt++) {
            CP_WAIT(1);
            __syncthreads();
            if (kt + 2 < nkt) stage_kv(kt + 2, (kt + 2) % 3);
            CP_COMMIT();

            const __half* Ks = sma + (kt % 3) * ASTAGE_H;
            const __half* Vs = Ks + KV_H;

            float s[8][4];
            #pragma unroll
            for (int nt = 0; nt < 8; nt++)
                #pragma unroll
                for (int i = 0; i < 4; i++) s[nt][i] = 0.f;

            #pragma unroll
            for (int kq = 0; kq < 4; kq++) {
                const int k0 = kq * 16;
                #pragma unroll
                for (int ntp = 0; ntp < 4; ntp++) {
                    const int n0 = ntp * 16;
                    uint32_t r4[4];
                    ldsm4(r4, sm_u32(Ks + (n0 + (sub >> 1) * 8 + lr) * SK
                                        + k0 + (sub & 1) * 8));
                    uint32_t b0[2] = {r4[0], r4[1]};
                    uint32_t b1[2] = {r4[2], r4[3]};
                    mma16(s[ntp * 2], qa[kq], b0, s[ntp * 2]);
                    mma16(s[ntp * 2 + 1], qa[kq], b1, s[ntp * 2 + 1]);
                }
            }

            #pragma unroll
            for (int nt = 0; nt < 8; nt++)
                #pragma unroll
                for (int i = 0; i < 4; i++) s[nt][i] *= sc;
            if (kt >= 2 * qt) {
                #pragma unroll
                for (int nt = 0; nt < 8; nt++) {
                    int colg = kt * 64 + nt * 8 + (lane & 3) * 2;
                    if (colg > gr0) s[nt][0] = -1e30f;
                    if (colg + 1 > gr0) s[nt][1] = -1e30f;
                    if (colg > gr1) s[nt][2] = -1e30f;
                    if (colg + 1 > gr1) s[nt][3] = -1e30f;
                }
            }

            float mx0 = -1e30f, mx1 = -1e30f;
            #pragma unroll
            for (int nt = 0; nt < 8; nt++) {
                mx0 = fmaxf(mx0, fmaxf(s[nt][0], s[nt][1]));
                mx1 = fmaxf(mx1, fmaxf(s[nt][2], s[nt][3]));
            }
            mx0 = fmaxf(mx0, __shfl_xor_sync(0xffffffffu, mx0, 1));
            mx0 = fmaxf(mx0, __shfl_xor_sync(0xffffffffu, mx0, 2));
            mx1 = fmaxf(mx1, __shfl_xor_sync(0xffffffffu, mx1, 1));
            mx1 = fmaxf(mx1, __shfl_xor_sync(0xffffffffu, mx1, 2));

            float nm0 = fmaxf(m0, mx0), nm1 = fmaxf(m1, mx1);
            float al0 = exp2f(m0 - nm0), al1 = exp2f(m1 - nm1);
            float sum0 = 0.f, sum1 = 0.f;
            uint32_t pa[8][2];

            #pragma unroll
            for (int nt = 0; nt < 8; nt++) {
                float p00 = exp2f(s[nt][0] - nm0);
                float p01 = exp2f(s[nt][1] - nm0);
                float p10 = exp2f(s[nt][2] - nm1);
                float p11 = exp2f(s[nt][3] - nm1);
                sum0 += p00 + p01;
                sum1 += p10 + p11;
                pa[nt][0] = h2u(__floats2half2_rn(p00, p01));
                pa[nt][1] = h2u(__floats2half2_rn(p10, p11));
            }
            sum0 += __shfl_xor_sync(0xffffffffu, sum0, 1);
            sum0 += __shfl_xor_sync(0xffffffffu, sum0, 2);
            sum1 += __shfl_xor_sync(0xffffffffu, sum1, 1);
            sum1 += __shfl_xor_sync(0xffffffffu, sum1, 2);

            l0 = l0 * al0 + sum0;
            l1 = l1 * al1 + sum1;
            m0 = nm0; m1 = nm1;
            #pragma unroll
            for (int nt = 0; nt < 8; nt++) {
                o[nt][0] *= al0; o[nt][1] *= al0;
                o[nt][2] *= al1; o[nt][3] *= al1;
            }

            #pragma unroll
            for (int kp = 0; kp < 4; kp++) {
                uint32_t af[4] = {pa[2 * kp][0], pa[2 * kp][1],
                                  pa[2 * kp + 1][0], pa[2 * kp + 1][1]};
                #pragma unroll
                for (int ntp = 0; ntp < 4; ntp++) {
                    const int n0 = ntp * 16;
                    uint32_t r4[4];
                    ldsm4t(r4, sm_u32(Vs + (kp * 16 + (sub & 1) * 8 + lr) * SK
                                         + n0 + (sub >> 1) * 8));
                    uint32_t b0[2] = {r4[0], r4[1]};
                    uint32_t b1[2] = {r4[2], r4[3]};
                    mma16(o[ntp * 2], af, b0, o[ntp * 2]);
                    mma16(o[ntp * 2 + 1], af, b1, o[ntp * 2 + 1]);
                }
            }
            __syncthreads();
        }

        // drain any outstanding cp.async groups before smem reuse next pass
        CP_WAIT(0);
        __syncthreads();

        float inv0 = 1.f / l0, inv1 = 1.f / l1;
        const int qrl = w * 16 + (lane >> 2);
        #pragma unroll
        for (int nt = 0; nt < 8; nt++) {
            int col = h * HD + nt * 8 + (lane & 3) * 2;
            *(__half2*)(outh + (size_t)(q0 + qrl) * DM + col) =
                __floats2half2_rn(o[nt][0] * inv0, o[nt][1] * inv0);
            *(__half2*)(outh + (size_t)(q0 + qrl + 8) * DM + col) =
                __floats2half2_rn(o[nt][2] * inv1, o[nt][3] * inv1);
        }
        __syncthreads();
    }
}

// ---------------------------------------------------------------------------
// Launch
// ---------------------------------------------------------------------------
extern "C" void kernel_launch(void* const* d_in, const int* in_sizes, int n_in,
                              void* d_out, int out_size)
{
    const float* x    = (const float*)d_in[0];
    const float* Wqkv = (const float*)d_in[1];
    const float* bqkv = (const float*)d_in[2];
    const float* Wout = (const float*)d_in[3];
    const float* bout = (const float*)d_in[4];
    float* out = (float*)d_out;

    __half *xh, *wqkvh, *wouth, *qkv, *attn;
    cudaGetSymbolAddress((void**)&xh,    g_xh);
    cudaGetSymbolAddress((void**)&wqkvh, g_wqkvh);
    cudaGetSymbolAddress((void**)&wouth, g_wouth);
    cudaGetSymbolAddress((void**)&qkv,   g_qkv);
    cudaGetSymbolAddress((void**)&attn,  g_attn);

    // 0) fp32 -> fp16
    {
        int n4;
        n4 = SQ * DM / 4;
        conv_h<<<(n4 + 255) / 256, 256>>>((const float4*)x, (__half2*)xh, n4);
        n4 = DM * D3 / 4;
        conv_h<<<(n4 + 255) / 256, 256>>>((const float4*)Wqkv, (__half2*)wqkvh, n4);
        n4 = DM * DM / 4;
        conv_h<<<(n4 + 255) / 256, 256>>>((const float4*)Wout, (__half2*)wouth, n4);
    }

    // 1) QKV projection -> fp16
    {
        cudaFuncSetAttribute(gemm_h<true>,
                             cudaFuncAttributeMaxDynamicSharedMemorySize, G_SMEM);
        dim3 grid(D3 / 128, SQ / 128);
        gemm_h<true><<<grid, 256, G_SMEM>>>(xh, wqkvh, bqkv, qkv, SQ, D3, DM);
    }

    // 2) Flash attention -> fp16 (paired q-tiles, balanced single wave)
    {
        cudaFuncSetAttribute(attn_h,
                             cudaFuncAttributeMaxDynamicSharedMemorySize, AT_SMEM);
        dim3 grid(16, NH);
        attn_h<<<grid, 256, AT_SMEM>>>(qkv, attn);
    }

    // 3) Output projection -> fp32
    {
        cudaFuncSetAttribute(gemm_h<false>,
                             cudaFuncAttributeMaxDynamicSharedMemorySize, G_SMEM);
        dim3 grid(DM / 128, SQ / 128);
        gemm_h<false><<<grid, 256, G_SMEM>>>(attn, wouth, bout, out, SQ, DM, DM);
    }
}

// round 7
// speedup vs baseline: 8.5927x; 1.0083x over previous
#include <cuda_runtime.h>
#include <cuda_fp16.h>
#include <cstdint>

#define SQ 4096
#define DM 1024
#define NH 16
#define HD 64
#define D3 3072

// fp16 scratch (allocation-free -> device globals)
__device__ __half g_xh[SQ * DM];
__device__ __half g_wqkvh[DM * D3];
__device__ __half g_wouth[DM * DM];
__device__ __half g_qkv[SQ * D3];
__device__ __half g_attn[SQ * DM];

// ---------------------------------------------------------------------------
// helpers
// ---------------------------------------------------------------------------
__device__ __forceinline__ void ldsm4(uint32_t* r, uint32_t a) {
    asm volatile("ldmatrix.sync.aligned.m8n8.x4.shared.b16 {%0,%1,%2,%3}, [%4];"
                 : "=r"(r[0]), "=r"(r[1]), "=r"(r[2]), "=r"(r[3]) : "r"(a));
}
__device__ __forceinline__ void ldsm4t(uint32_t* r, uint32_t a) {
    asm volatile("ldmatrix.sync.aligned.m8n8.x4.trans.shared.b16 {%0,%1,%2,%3}, [%4];"
                 : "=r"(r[0]), "=r"(r[1]), "=r"(r[2]), "=r"(r[3]) : "r"(a));
}
__device__ __forceinline__ void ldsm2t(uint32_t* r, uint32_t a) {
    asm volatile("ldmatrix.sync.aligned.m8n8.x2.trans.shared.b16 {%0,%1}, [%2];"
                 : "=r"(r[0]), "=r"(r[1]) : "r"(a));
}
__device__ __forceinline__ void mma16(float* d, const uint32_t* a,
                                      const uint32_t* b, const float* c) {
    asm volatile(
        "mma.sync.aligned.m16n8k16.row.col.f32.f16.f16.f32 "
        "{%0,%1,%2,%3}, {%4,%5,%6,%7}, {%8,%9}, {%10,%11,%12,%13};"
        : "=f"(d[0]), "=f"(d[1]), "=f"(d[2]), "=f"(d[3])
        : "r"(a[0]), "r"(a[1]), "r"(a[2]), "r"(a[3]),
          "r"(b[0]), "r"(b[1]),
          "f"(c[0]), "f"(c[1]), "f"(c[2]), "f"(c[3]));
}
__device__ __forceinline__ void cpa16(uint32_t saddr, const void* gptr) {
    asm volatile("cp.async.cg.shared.global [%0], [%1], 16;"
                 :: "r"(saddr), "l"(gptr));
}
#define CP_COMMIT() asm volatile("cp.async.commit_group;")
#define CP_WAIT(n)  asm volatile("cp.async.wait_group %0;" :: "n"(n))

__device__ __forceinline__ uint32_t h2u(__half2 h) {
    return *reinterpret_cast<uint32_t*>(&h);
}
__device__ __forceinline__ uint32_t sm_u32(const void* p) {
    return (uint32_t)__cvta_generic_to_shared(p);
}

// fp32 -> fp16 conversion
__global__ void conv_h(const float4* __restrict__ in,
                       __half2* __restrict__ out, int n4)
{
    int i = blockIdx.x * blockDim.x + threadIdx.x;
    if (i < n4) {
        float4 v = in[i];
        out[2 * i]     = __floats2half2_rn(v.x, v.y);
        out[2 * i + 1] = __floats2half2_rn(v.z, v.w);
    }
}

// ---------------------------------------------------------------------------
// FP16 GEMM: C = A[M,K] @ B[K,N] + bias. 128x128x64 tile, 256 thr,
// warp tile 64x32, 3-stage cp.async ring, ldmatrix fragments.
// ---------------------------------------------------------------------------
#define SA 72
#define SB 136
#define GSTAGE_H (128 * SA + 64 * SB)
#define G_SMEM (3 * GSTAGE_H * 2)

template <bool OUT_HALF>
__global__ void __launch_bounds__(256, 2) gemm_h(
    const __half* __restrict__ A, const __half* __restrict__ B,
    const float* __restrict__ bias, void* __restrict__ Cv,
    int M, int N, int K)
{
    extern __shared__ __half smg[];

    const int tid = threadIdx.x;
    const int lane = tid & 31;
    const int w = tid >> 5;
    const int wm = w >> 2;
    const int wn = w & 3;
    const int bm = blockIdx.y * 128;
    const int bn = blockIdx.x * 128;
    const int sub = lane >> 3;
    const int lr = lane & 7;

    float acc[4][4][4];
    #pragma unroll
    for (int mt = 0; mt < 4; mt++)
        #pragma unroll
        for (int nt = 0; nt < 4; nt++)
            #pragma unroll
            for (int i = 0; i < 4; i++) acc[mt][nt][i] = 0.f;

    auto stage = [&](int kb, int s) {
        __half* As = smg + s * GSTAGE_H;
        __half* Bs = As + 128 * SA;
        #pragma unroll
        for (int p = 0; p < 4; p++) {
            int c = tid + p * 256;
            int r = c >> 3, col = (c & 7) * 8;
            cpa16(sm_u32(As + r * SA + col), A + (size_t)(bm + r) * K + kb * 64 + col);
        }
        #pragma unroll
        for (int p = 0; p < 4; p++) {
            int c = tid + p * 256;
            int r = c >> 4, col = (c & 15) * 8;
            cpa16(sm_u32(Bs + r * SB + col), B + (size_t)(kb * 64 + r) * N + bn + col);
        }
    };

    const int niter = K / 64;
    stage(0, 0); CP_COMMIT();
    stage(1, 1); CP_COMMIT();

    for (int it = 0; it < niter; it++) {
        CP_WAIT(1);
        __syncthreads();
        if (it + 2 < niter) stage(it + 2, (it + 2) % 3);
        CP_COMMIT();

        const __half* As = smg + (it % 3) * GSTAGE_H;
        const __half* Bs = As + 128 * SA;

        #pragma unroll
        for (int ks = 0; ks < 4; ks++) {
            const int k0 = ks * 16;
            uint32_t af[4][4], bf[4][2];
            #pragma unroll
            for (int mt = 0; mt < 4; mt++) {
                int row = wm * 64 + mt * 16 + (sub & 1) * 8 + lr;
                ldsm4(af[mt], sm_u32(As + row * SA + k0 + (sub >> 1) * 8));
            }
            #pragma unroll
            for (int ntp = 0; ntp < 2; ntp++) {
                int n0 = wn * 32 + ntp * 16;
                uint32_t r4[4];
                ldsm4t(r4, sm_u32(Bs + (k0 + (sub & 1) * 8 + lr) * SB
                                     + n0 + (sub >> 1) * 8));
                bf[ntp * 2][0] = r4[0]; bf[ntp * 2][1] = r4[1];
                bf[ntp * 2 + 1][0] = r4[2]; bf[ntp * 2 + 1][1] = r4[3];
            }
            #pragma unroll
            for (int mt = 0; mt < 4; mt++)
                #pragma unroll
                for (int nt = 0; nt < 4; nt++)
                    mma16(acc[mt][nt], af[mt], bf[nt], acc[mt][nt]);
        }
    }

    __syncthreads();
    #pragma unroll
    for (int mt = 0; mt < 4; mt++) {
        int row = bm + wm * 64 + mt * 16 + (lane >> 2);
        #pragma unroll
        for (int nt = 0; nt < 4; nt++) {
            int col = bn + wn * 32 + nt * 8 + (lane & 3) * 2;
            float b0 = bias[col], b1 = bias[col + 1];
            if (OUT_HALF) {
                __half* C = (__half*)Cv;
                *(__half2*)(C + (size_t)row * N + col) =
                    __floats2half2_rn(acc[mt][nt][0] + b0, acc[mt][nt][1] + b1);
                *(__half2*)(C + (size_t)(row + 8) * N + col) =
                    __floats2half2_rn(acc[mt][nt][2] + b0, acc[mt][nt][3] + b1);
            } else {
                float* C = (float*)Cv;
                *(float2*)(C + (size_t)row * N + col) =
                    make_float2(acc[mt][nt][0] + b0, acc[mt][nt][1] + b1);
                *(float2*)(C + (size_t)(row + 8) * N + col) =
                    make_float2(acc[mt][nt][2] + b0, acc[mt][nt][3] + b1);
            }
        }
    }
}

// ---------------------------------------------------------------------------
// Flash attention, fp16 mma, P register-resident, f16x2 exp, l-via-mma.
// Grid (16, NH); each CTA does qt = 31-bx then qt = bx (66 iters, balanced).
// V tiles carry a constant ones-column at dim 64 (cols 65-71 zero) so the
// PV mma's extra n=8 block accumulates the softmax denominator in o_l.
// ---------------------------------------------------------------------------
#define SK 72
#define KV_H (64 * SK)
#define ASTAGE_H (2 * KV_H)
#define AT_SMEM (3 * ASTAGE_H * 2)

__global__ void __launch_bounds__(256, 2) attn_h(
    const __half* __restrict__ qkv, __half* __restrict__ outh)
{
    extern __shared__ __half sma[];

    const int tid = threadIdx.x;
    const int lane = tid & 31;
    const int w = tid >> 5;
    const int sub = lane >> 3;
    const int lr = lane & 7;
    const int h = blockIdx.y;

    const __half* qb = qkv + h * HD;
    const __half* kb = qkv + DM + h * HD;
    const __half* vb = qkv + 2 * DM + h * HD;

    // one-time init: V cols 64..71 = [1, 0, 0, ...] in all 3 slots.
    // cp.async staging only ever writes cols 0..63, so these persist.
    #pragma unroll
    for (int s = 0; s < 3; s++) {
        __half* Vs = sma + s * ASTAGE_H + KV_H;
        for (int i = tid; i < 64 * 8; i += 256) {
            int r = i >> 3, c = 64 + (i & 7);
            Vs[r * SK + c] = (c == 64) ? __float2half(1.f) : __float2half(0.f);
        }
    }

    #pragma unroll 1
    for (int pass = 0; pass < 2; pass++) {
        const int qt = (pass == 0) ? (31 - (int)blockIdx.x) : (int)blockIdx.x;
        const int q0 = qt * 128;

        // --- Stage Q (128x64, cols 0-63 only) and extract register a-frags ---
        for (int p = 0; p < 4; p++) {
            int c = tid + p * 256;
            int r = c >> 3, col = (c & 7) * 8;
            cpa16(sm_u32(sma + r * SK + col), qb + (size_t)(q0 + r) * D3 + col);
        }
        CP_COMMIT(); CP_WAIT(0);
        __syncthreads();

        uint32_t qa[4][4];
        #pragma unroll
        for (int kq = 0; kq < 4; kq++) {
            int row = w * 16 + (sub & 1) * 8 + lr;
            ldsm4(qa[kq], sm_u32(sma + row * SK + kq * 16 + (sub >> 1) * 8));
        }
        __syncthreads();

        auto stage_kv = [&](int kt, int s) {
            __half* Ks = sma + s * ASTAGE_H;
            __half* Vs = Ks + KV_H;
            #pragma unroll
            for (int p = 0; p < 2; p++) {
                int c = tid + p * 256;
                int r = c >> 3, col = (c & 7) * 8;
                size_t g = (size_t)(kt * 64 + r) * D3 + col;
                cpa16(sm_u32(Ks + r * SK + col), kb + g);
                cpa16(sm_u32(Vs + r * SK + col), vb + g);
            }
        };

        const int nkt = 2 * qt + 2;
        stage_kv(0, 0); CP_COMMIT();
        stage_kv(1, 1); CP_COMMIT();

        float m0 = -1e30f, m1 = -1e30f;
        float o[8][4], o_l[4];
        #pragma unroll
        for (int nt = 0; nt < 8; nt++)
            #pragma unroll
            for (int i = 0; i < 4; i++) o[nt][i] = 0.f;
        #pragma unroll
        for (int i = 0; i < 4; i++) o_l[i] = 0.f;

        const float sc = 0.125f * 1.44269504088896f;  // scale * log2(e)
        const int gr0 = q0 + w * 16 + (lane >> 2);
        const int gr1 = gr0 + 8;

        for (int kt = 0; kt < nkt; kt++) {
            CP_WAIT(1);
            __syncthreads();
            if (kt + 2 < nkt) stage_kv(kt + 2, (kt + 2) % 3);
            CP_COMMIT();

            const __half* Ks = sma + (kt % 3) * ASTAGE_H;
            const __half* Vs = Ks + KV_H;

            // ---- S = Q @ K^T ----
            float s[8][4];
            #pragma unroll
            for (int nt = 0; nt < 8; nt++)
                #pragma unroll
                for (int i = 0; i < 4; i++) s[nt][i] = 0.f;

            #pragma unroll
            for (int kq = 0; kq < 4; kq++) {
                const int k0 = kq * 16;
                #pragma unroll
                for (int ntp = 0; ntp < 4; ntp++) {
                    const int n0 = ntp * 16;
                    uint32_t r4[4];
                    ldsm4(r4, sm_u32(Ks + (n0 + (sub >> 1) * 8 + lr) * SK
                                        + k0 + (sub & 1) * 8));
                    uint32_t b0[2] = {r4[0], r4[1]};
                    uint32_t b1[2] = {r4[2], r4[3]};
                    mma16(s[ntp * 2], qa[kq], b0, s[ntp * 2]);
                    mma16(s[ntp * 2 + 1], qa[kq], b1, s[ntp * 2 + 1]);
                }
            }

            // ---- scale (log2 domain) + causal mask on diagonal band ----
            #pragma unroll
            for (int nt = 0; nt < 8; nt++)
                #pragma unroll
                for (int i = 0; i < 4; i++) s[nt][i] *= sc;
            if (kt >= 2 * qt) {
                #pragma unroll
                for (int nt = 0; nt < 8; nt++) {
                    int colg = kt * 64 + nt * 8 + (lane & 3) * 2;
                    if (colg > gr0) s[nt][0] = -1e30f;
                    if (colg + 1 > gr0) s[nt][1] = -1e30f;
                    if (colg > gr1) s[nt][2] = -1e30f;
                    if (colg + 1 > gr1) s[nt][3] = -1e30f;
                }
            }

            // ---- online softmax: row max, then f16x2 exp straight into frags
            float mx0 = -1e30f, mx1 = -1e30f;
            #pragma unroll
            for (int nt = 0; nt < 8; nt++) {
                mx0 = fmaxf(mx0, fmaxf(s[nt][0], s[nt][1]));
                mx1 = fmaxf(mx1, fmaxf(s[nt][2], s[nt][3]));
            }
            mx0 = fmaxf(mx0, __shfl_xor_sync(0xffffffffu, mx0, 1));
            mx0 = fmaxf(mx0, __shfl_xor_sync(0xffffffffu, mx0, 2));
            mx1 = fmaxf(mx1, __shfl_xor_sync(0xffffffffu, mx1, 1));
            mx1 = fmaxf(mx1, __shfl_xor_sync(0xffffffffu, mx1, 2));

            float nm0 = fmaxf(m0, mx0), nm1 = fmaxf(m1, mx1);
            float al0 = exp2f(m0 - nm0), al1 = exp2f(m1 - nm1);
            m0 = nm0; m1 = nm1;

            uint32_t pa[8][2];
            #pragma unroll
            for (int nt = 0; nt < 8; nt++) {
                __half2 hp0 = h2exp2(__floats2half2_rn(s[nt][0] - nm0,
                                                       s[nt][1] - nm0));
                __half2 hp1 = h2exp2(__floats2half2_rn(s[nt][2] - nm1,
                                                       s[nt][3] - nm1));
                pa[nt][0] = h2u(hp0);
                pa[nt][1] = h2u(hp1);
            }

            #pragma unroll
            for (int nt = 0; nt < 8; nt++) {
                o[nt][0] *= al0; o[nt][1] *= al0;
                o[nt][2] *= al1; o[nt][3] *= al1;
            }
            o_l[0] *= al0; o_l[1] *= al0;
            o_l[2] *= al1; o_l[3] *= al1;

            // ---- O += P @ V (plus ones-column -> o_l accumulates l) ----
            #pragma unroll
            for (int kp = 0; kp < 4; kp++) {
                uint32_t af[4] = {pa[2 * kp][0], pa[2 * kp][1],
                                  pa[2 * kp + 1][0], pa[2 * kp + 1][1]};
                #pragma unroll
                for (int ntp = 0; ntp < 4; ntp++) {
                    const int n0 = ntp * 16;
                    uint32_t r4[4];
                    ldsm4t(r4, sm_u32(Vs + (kp * 16 + (sub & 1) * 8 + lr) * SK
                                         + n0 + (sub >> 1) * 8));
                    uint32_t b0[2] = {r4[0], r4[1]};
                    uint32_t b1[2] = {r4[2], r4[3]};
                    mma16(o[ntp * 2], af, b0, o[ntp * 2]);
                    mma16(o[ntp * 2 + 1], af, b1, o[ntp * 2 + 1]);
                }
                uint32_t bl[2];
                ldsm2t(bl, sm_u32(Vs + (kp * 16 + (lane & 15)) * SK + 64));
                mma16(o_l, af, bl, o_l);
            }
        }

        // drain outstanding cp.async before smem reuse next pass
        CP_WAIT(0);
        __syncthreads();

        // l lives in o_l[0] (row set 0) / o_l[2] (row set 1) of quad-lane 0
        float l0 = __shfl_sync(0xffffffffu, o_l[0], lane & ~3);
        float l1 = __shfl_sync(0xffffffffu, o_l[2], lane & ~3);
        float inv0 = 1.f / l0, inv1 = 1.f / l1;
        const int qrl = w * 16 + (lane >> 2);
        #pragma unroll
        for (int nt = 0; nt < 8; nt++) {
            int col = h * HD + nt * 8 + (lane & 3) * 2;
            *(__half2*)(outh + (size_t)(q0 + qrl) * DM + col) =
                __floats2half2_rn(o[nt][0] * inv0, o[nt][1] * inv0);
            *(__half2*)(outh + (size_t)(q0 + qrl + 8) * DM + col) =
                __floats2half2_rn(o[nt][2] * inv1, o[nt][3] * inv1);
        }
        __syncthreads();
    }
}

// ---------------------------------------------------------------------------
// Launch
// ---------------------------------------------------------------------------
extern "C" void kernel_launch(void* const* d_in, const int* in_sizes, int n_in,
                              void* d_out, int out_size)
{
    const float* x    = (const float*)d_in[0];
    const float* Wqkv = (const float*)d_in[1];
    const float* bqkv = (const float*)d_in[2];
    const float* Wout = (const float*)d_in[3];
    const float* bout = (const float*)d_in[4];
    float* out = (float*)d_out;

    __half *xh, *wqkvh, *wouth, *qkv, *attn;
    cudaGetSymbolAddress((void**)&xh,    g_xh);
    cudaGetSymbolAddress((void**)&wqkvh, g_wqkvh);
    cudaGetSymbolAddress((void**)&wouth, g_wouth);
    cudaGetSymbolAddress((void**)&qkv,   g_qkv);
    cudaGetSymbolAddress((void**)&attn,  g_attn);

    // 0) fp32 -> fp16
    {
        int n4;
        n4 = SQ * DM / 4;
        conv_h<<<(n4 + 255) / 256, 256>>>((const float4*)x, (__half2*)xh, n4);
        n4 = DM * D3 / 4;
        conv_h<<<(n4 + 255) / 256, 256>>>((const float4*)Wqkv, (__half2*)wqkvh, n4);
        n4 = DM * DM / 4;
        conv_h<<<(n4 + 255) / 256, 256>>>((const float4*)Wout, (__half2*)wouth, n4);
    }

    // 1) QKV projection -> fp16
    {
        cudaFuncSetAttribute(gemm_h<true>,
                             cudaFuncAttributeMaxDynamicSharedMemorySize, G_SMEM);
        dim3 grid(D3 / 128, SQ / 128);
        gemm_h<true><<<grid, 256, G_SMEM>>>(xh, wqkvh, bqkv, qkv, SQ, D3, DM);
    }

    // 2) Flash attention -> fp16
    {
        cudaFuncSetAttribute(attn_h,
                             cudaFuncAttributeMaxDynamicSharedMemorySize, AT_SMEM);
        dim3 grid(16, NH);
        attn_h<<<grid, 256, AT_SMEM>>>(qkv, attn);
    }

    // 3) Output projection -> fp32
    {
        cudaFuncSetAttribute(gemm_h<false>,
                             cudaFuncAttributeMaxDynamicSharedMemorySize, G_SMEM);
        dim3 grid(DM / 128, SQ / 128);
        gemm_h<false><<<grid, 256, G_SMEM>>>(attn, wouth, bout, out, SQ, DM, DM);
    }
}

// round 8
// speedup vs baseline: 8.8580x; 1.0309x over previous
#include <cuda_runtime.h>
#include <cuda_fp16.h>
#include <cstdint>

#define SQ 4096
#define DM 1024
#define NH 16
#define HD 64
#define D3 3072

// fp16 scratch (allocation-free -> device globals)
__device__ __half g_xh[SQ * DM];
__device__ __half g_wqkvh[DM * D3];
__device__ __half g_wouth[DM * DM];
__device__ __half g_qkv[SQ * D3];
__device__ __half g_attn[SQ * DM];
__device__ unsigned int g_tile_ctr;   // attention work-queue cursor

// ---------------------------------------------------------------------------
// helpers
// ---------------------------------------------------------------------------
__device__ __forceinline__ void ldsm4(uint32_t* r, uint32_t a) {
    asm volatile("ldmatrix.sync.aligned.m8n8.x4.shared.b16 {%0,%1,%2,%3}, [%4];"
                 : "=r"(r[0]), "=r"(r[1]), "=r"(r[2]), "=r"(r[3]) : "r"(a));
}
__device__ __forceinline__ void ldsm4t(uint32_t* r, uint32_t a) {
    asm volatile("ldmatrix.sync.aligned.m8n8.x4.trans.shared.b16 {%0,%1,%2,%3}, [%4];"
                 : "=r"(r[0]), "=r"(r[1]), "=r"(r[2]), "=r"(r[3]) : "r"(a));
}
__device__ __forceinline__ void ldsm2t(uint32_t* r, uint32_t a) {
    asm volatile("ldmatrix.sync.aligned.m8n8.x2.trans.shared.b16 {%0,%1}, [%2];"
                 : "=r"(r[0]), "=r"(r[1]) : "r"(a));
}
__device__ __forceinline__ void mma16(float* d, const uint32_t* a,
                                      const uint32_t* b, const float* c) {
    asm volatile(
        "mma.sync.aligned.m16n8k16.row.col.f32.f16.f16.f32 "
        "{%0,%1,%2,%3}, {%4,%5,%6,%7}, {%8,%9}, {%10,%11,%12,%13};"
        : "=f"(d[0]), "=f"(d[1]), "=f"(d[2]), "=f"(d[3])
        : "r"(a[0]), "r"(a[1]), "r"(a[2]), "r"(a[3]),
          "r"(b[0]), "r"(b[1]),
          "f"(c[0]), "f"(c[1]), "f"(c[2]), "f"(c[3]));
}
__device__ __forceinline__ void cpa16(uint32_t saddr, const void* gptr) {
    asm volatile("cp.async.cg.shared.global [%0], [%1], 16;"
                 :: "r"(saddr), "l"(gptr));
}
#define CP_COMMIT() asm volatile("cp.async.commit_group;")
#define CP_WAIT(n)  asm volatile("cp.async.wait_group %0;" :: "n"(n))

__device__ __forceinline__ uint32_t h2u(__half2 h) {
    return *reinterpret_cast<uint32_t*>(&h);
}
__device__ __forceinline__ uint32_t sm_u32(const void* p) {
    return (uint32_t)__cvta_generic_to_shared(p);
}

// fp32 -> fp16 conversion
__global__ void conv_h(const float4* __restrict__ in,
                       __half2* __restrict__ out, int n4)
{
    int i = blockIdx.x * blockDim.x + threadIdx.x;
    if (i < n4) {
        float4 v = in[i];
        out[2 * i]     = __floats2half2_rn(v.x, v.y);
        out[2 * i + 1] = __floats2half2_rn(v.z, v.w);
    }
}

// ---------------------------------------------------------------------------
// FP16 GEMM: C = A[M,K] @ B[K,N] + bias. 128x128x64 tile, 256 thr,
// warp tile 64x32, 3-stage cp.async ring, ldmatrix fragments.
// The OUT_HALF (QKV) instance also resets the attention work-queue counter.
// ---------------------------------------------------------------------------
#define SA 72
#define SB 136
#define GSTAGE_H (128 * SA + 64 * SB)
#define G_SMEM (3 * GSTAGE_H * 2)

template <bool OUT_HALF>
__global__ void __launch_bounds__(256, 2) gemm_h(
    const __half* __restrict__ A, const __half* __restrict__ B,
    const float* __restrict__ bias, void* __restrict__ Cv,
    int M, int N, int K)
{
    extern __shared__ __half smg[];

    const int tid = threadIdx.x;
    const int lane = tid & 31;
    const int w = tid >> 5;
    const int wm = w >> 2;
    const int wn = w & 3;
    const int bm = blockIdx.y * 128;
    const int bn = blockIdx.x * 128;
    const int sub = lane >> 3;
    const int lr = lane & 7;

    // deterministic reset of the attention work-queue (QKV runs before attn)
    if (OUT_HALF && blockIdx.x == 0 && blockIdx.y == 0 && tid == 0)
        g_tile_ctr = 0;

    float acc[4][4][4];
    #pragma unroll
    for (int mt = 0; mt < 4; mt++)
        #pragma unroll
        for (int nt = 0; nt < 4; nt++)
            #pragma unroll
            for (int i = 0; i < 4; i++) acc[mt][nt][i] = 0.f;

    auto stage = [&](int kb, int s) {
        __half* As = smg + s * GSTAGE_H;
        __half* Bs = As + 128 * SA;
        #pragma unroll
        for (int p = 0; p < 4; p++) {
            int c = tid + p * 256;
            int r = c >> 3, col = (c & 7) * 8;
            cpa16(sm_u32(As + r * SA + col), A + (size_t)(bm + r) * K + kb * 64 + col);
        }
        #pragma unroll
        for (int p = 0; p < 4; p++) {
            int c = tid + p * 256;
            int r = c >> 4, col = (c & 15) * 8;
            cpa16(sm_u32(Bs + r * SB + col), B + (size_t)(kb * 64 + r) * N + bn + col);
        }
    };

    const int niter = K / 64;
    stage(0, 0); CP_COMMIT();
    stage(1, 1); CP_COMMIT();

    for (int it = 0; it < niter; it++) {
        CP_WAIT(1);
        __syncthreads();
        if (it + 2 < niter) stage(it + 2, (it + 2) % 3);
        CP_COMMIT();

        const __half* As = smg + (it % 3) * GSTAGE_H;
        const __half* Bs = As + 128 * SA;

        #pragma unroll
        for (int ks = 0; ks < 4; ks++) {
            const int k0 = ks * 16;
            uint32_t af[4][4], bf[4][2];
            #pragma unroll
            for (int mt = 0; mt < 4; mt++) {
                int row = wm * 64 + mt * 16 + (sub & 1) * 8 + lr;
                ldsm4(af[mt], sm_u32(As + row * SA + k0 + (sub >> 1) * 8));
            }
            #pragma unroll
            for (int ntp = 0; ntp < 2; ntp++) {
                int n0 = wn * 32 + ntp * 16;
                uint32_t r4[4];
                ldsm4t(r4, sm_u32(Bs + (k0 + (sub & 1) * 8 + lr) * SB
                                     + n0 + (sub >> 1) * 8));
                bf[ntp * 2][0] = r4[0]; bf[ntp * 2][1] = r4[1];
                bf[ntp * 2 + 1][0] = r4[2]; bf[ntp * 2 + 1][1] = r4[3];
            }
            #pragma unroll
            for (int mt = 0; mt < 4; mt++)
                #pragma unroll
                for (int nt = 0; nt < 4; nt++)
                    mma16(acc[mt][nt], af[mt], bf[nt], acc[mt][nt]);
        }
    }

    __syncthreads();
    #pragma unroll
    for (int mt = 0; mt < 4; mt++) {
        int row = bm + wm * 64 + mt * 16 + (lane >> 2);
        #pragma unroll
        for (int nt = 0; nt < 4; nt++) {
            int col = bn + wn * 32 + nt * 8 + (lane & 3) * 2;
            float b0 = bias[col], b1 = bias[col + 1];
            if (OUT_HALF) {
                __half* C = (__half*)Cv;
                *(__half2*)(C + (size_t)row * N + col) =
                    __floats2half2_rn(acc[mt][nt][0] + b0, acc[mt][nt][1] + b1);
                *(__half2*)(C + (size_t)(row + 8) * N + col) =
                    __floats2half2_rn(acc[mt][nt][2] + b0, acc[mt][nt][3] + b1);
            } else {
                float* C = (float*)Cv;
                *(float2*)(C + (size_t)row * N + col) =
                    make_float2(acc[mt][nt][0] + b0, acc[mt][nt][1] + b1);
                *(float2*)(C + (size_t)(row + 8) * N + col) =
                    make_float2(acc[mt][nt][2] + b0, acc[mt][nt][3] + b1);
            }
        }
    }
}

// ---------------------------------------------------------------------------
// Flash attention, persistent work-queue version.
// 296 CTAs (148 SMs x 2). Tiles = 512 (head, qtile) pairs, heavy-first:
// idx -> qt = 31 - idx/16, h = idx%16.  4-stage K/V cp.async ring.
// V tiles carry a ones-column at dim 64 -> PV mma accumulates denominator.
// ---------------------------------------------------------------------------
#define SK 72
#define KV_H (64 * SK)
#define ASTAGE_H (2 * KV_H)
#define NSTG 4
#define AT_SMEM (NSTG * ASTAGE_H * 2)
#define NTILES 512

__global__ void __launch_bounds__(256, 2) attn_h(
    const __half* __restrict__ qkv, __half* __restrict__ outh)
{
    extern __shared__ __half sma[];
    __shared__ unsigned s_idx;

    const int tid = threadIdx.x;
    const int lane = tid & 31;
    const int w = tid >> 5;
    const int sub = lane >> 3;
    const int lr = lane & 7;

    // one-time init: V cols 64..71 = [1,0,...] in all slots (staging never
    // writes cols >= 64, Q staging only touches the K region of slot 0).
    #pragma unroll
    for (int s = 0; s < NSTG; s++) {
        __half* Vs = sma + s * ASTAGE_H + KV_H;
        for (int i = tid; i < 64 * 8; i += 256) {
            int r = i >> 3, c = 64 + (i & 7);
            Vs[r * SK + c] = (c == 64) ? __float2half(1.f) : __float2half(0.f);
        }
    }
    __syncthreads();

    // constant ones-column b-fragment (identical for every tile/iter)
    uint32_t bl[2];
    ldsm2t(bl, sm_u32(sma + KV_H + (lane & 15) * SK + 64));

    const float sc = 0.125f * 1.44269504088896f;  // scale * log2(e)

    while (true) {
        if (tid == 0) s_idx = atomicAdd(&g_tile_ctr, 1u);
        __syncthreads();
        const unsigned idx = s_idx;
        if (idx >= NTILES) break;

        const int qt = 31 - (int)(idx >> 4);   // heavy tiles first
        const int h = (int)(idx & 15);
        const int q0 = qt * 128;

        const __half* qb = qkv + h * HD;
        const __half* kb = qkv + DM + h * HD;
        const __half* vb = qkv + 2 * DM + h * HD;

        // --- Stage Q (128x64) into slot-0 K region, extract a-frags ---
        for (int p = 0; p < 4; p++) {
            int c = tid + p * 256;
            int r = c >> 3, col = (c & 7) * 8;
            cpa16(sm_u32(sma + r * SK + col), qb + (size_t)(q0 + r) * D3 + col);
        }
        CP_COMMIT(); CP_WAIT(0);
        __syncthreads();

        uint32_t qa[4][4];
        #pragma unroll
        for (int kq = 0; kq < 4; kq++) {
            int row = w * 16 + (sub & 1) * 8 + lr;
            ldsm4(qa[kq], sm_u32(sma + row * SK + kq * 16 + (sub >> 1) * 8));
        }
        __syncthreads();

        auto stage_kv = [&](int kt, int s) {
            __half* Ks = sma + s * ASTAGE_H;
            __half* Vs = Ks + KV_H;
            #pragma unroll
            for (int p = 0; p < 2; p++) {
                int c = tid + p * 256;
                int r = c >> 3, col = (c & 7) * 8;
                size_t g = (size_t)(kt * 64 + r) * D3 + col;
                cpa16(sm_u32(Ks + r * SK + col), kb + g);
                cpa16(sm_u32(Vs + r * SK + col), vb + g);
            }
        };

        const int nkt = 2 * qt + 2;     // >= 2
        stage_kv(0, 0); CP_COMMIT();
        stage_kv(1, 1); CP_COMMIT();
        if (nkt > 2) stage_kv(2, 2);
        CP_COMMIT();

        float m0 = -1e30f, m1 = -1e30f;
        float o[8][4], o_l[4];
        #pragma unroll
        for (int nt = 0; nt < 8; nt++)
            #pragma unroll
            for (int i = 0; i < 4; i++) o[nt][i] = 0.f;
        #pragma unroll
        for (int i = 0; i < 4; i++) o_l[i] = 0.f;

        const int gr0 = q0 + w * 16 + (lane >> 2);
        const int gr1 = gr0 + 8;

        for (int kt = 0; kt < nkt; kt++) {
            CP_WAIT(2);
            __syncthreads();
            if (kt + 3 < nkt) stage_kv(kt + 3, (kt + 3) % NSTG);
            CP_COMMIT();

            const __half* Ks = sma + (kt % NSTG) * ASTAGE_H;
            const __half* Vs = Ks + KV_H;

            // ---- S = Q @ K^T ----
            float s[8][4];
            #pragma unroll
            for (int nt = 0; nt < 8; nt++)
                #pragma unroll
                for (int i = 0; i < 4; i++) s[nt][i] = 0.f;

            #pragma unroll
            for (int kq = 0; kq < 4; kq++) {
                const int k0 = kq * 16;
                #pragma unroll
                for (int ntp = 0; ntp < 4; ntp++) {
                    const int n0 = ntp * 16;
                    uint32_t r4[4];
                    ldsm4(r4, sm_u32(Ks + (n0 + (sub >> 1) * 8 + lr) * SK
                                        + k0 + (sub & 1) * 8));
                    uint32_t b0[2] = {r4[0], r4[1]};
                    uint32_t b1[2] = {r4[2], r4[3]};
                    mma16(s[ntp * 2], qa[kq], b0, s[ntp * 2]);
                    mma16(s[ntp * 2 + 1], qa[kq], b1, s[ntp * 2 + 1]);
                }
            }

            // ---- scale (log2 domain) + causal mask on diagonal band ----
            #pragma unroll
            for (int nt = 0; nt < 8; nt++)
                #pragma unroll
                for (int i = 0; i < 4; i++) s[nt][i] *= sc;
            if (kt >= 2 * qt) {
                #pragma unroll
                for (int nt = 0; nt < 8; nt++) {
                    int colg = kt * 64 + nt * 8 + (lane & 3) * 2;
                    if (colg > gr0) s[nt][0] = -1e30f;
                    if (colg + 1 > gr0) s[nt][1] = -1e30f;
                    if (colg > gr1) s[nt][2] = -1e30f;
                    if (colg + 1 > gr1) s[nt][3] = -1e30f;
                }
            }

            // ---- online softmax ----
            float mx0 = -1e30f, mx1 = -1e30f;
            #pragma unroll
            for (int nt = 0; nt < 8; nt++) {
                mx0 = fmaxf(mx0, fmaxf(s[nt][0], s[nt][1]));
                mx1 = fmaxf(mx1, fmaxf(s[nt][2], s[nt][3]));
            }
            mx0 = fmaxf(mx0, __shfl_xor_sync(0xffffffffu, mx0, 1));
            mx0 = fmaxf(mx0, __shfl_xor_sync(0xffffffffu, mx0, 2));
            mx1 = fmaxf(mx1, __shfl_xor_sync(0xffffffffu, mx1, 1));
            mx1 = fmaxf(mx1, __shfl_xor_sync(0xffffffffu, mx1, 2));

            float nm0 = fmaxf(m0, mx0), nm1 = fmaxf(m1, mx1);
            float al0 = exp2f(m0 - nm0), al1 = exp2f(m1 - nm1);
            m0 = nm0; m1 = nm1;

            uint32_t pa[8][2];
            #pragma unroll
            for (int nt = 0; nt < 8; nt++) {
                __half2 hp0 = h2exp2(__floats2half2_rn(s[nt][0] - nm0,
                                                       s[nt][1] - nm0));
                __half2 hp1 = h2exp2(__floats2half2_rn(s[nt][2] - nm1,
                                                       s[nt][3] - nm1));
                pa[nt][0] = h2u(hp0);
                pa[nt][1] = h2u(hp1);
            }

            #pragma unroll
            for (int nt = 0; nt < 8; nt++) {
                o[nt][0] *= al0; o[nt][1] *= al0;
                o[nt][2] *= al1; o[nt][3] *= al1;
            }
            o_l[0] *= al0; o_l[1] *= al0;
            o_l[2] *= al1; o_l[3] *= al1;

            // ---- O += P @ V (ones-column -> o_l accumulates l) ----
            #pragma unroll
            for (int kp = 0; kp < 4; kp++) {
                uint32_t af[4] = {pa[2 * kp][0], pa[2 * kp][1],
                                  pa[2 * kp + 1][0], pa[2 * kp + 1][1]};
                #pragma unroll
                for (int ntp = 0; ntp < 4; ntp++) {
                    const int n0 = ntp * 16;
                    uint32_t r4[4];
                    ldsm4t(r4, sm_u32(Vs + (kp * 16 + (sub & 1) * 8 + lr) * SK
                                         + n0 + (sub >> 1) * 8));
                    uint32_t b0[2] = {r4[0], r4[1]};
                    uint32_t b1[2] = {r4[2], r4[3]};
                    mma16(o[ntp * 2], af, b0, o[ntp * 2]);
                    mma16(o[ntp * 2 + 1], af, b1, o[ntp * 2 + 1]);
                }
                mma16(o_l, af, bl, o_l);
            }
        }

        // drain outstanding cp.async before next tile reuses smem
        CP_WAIT(0);
        __syncthreads();

        float l0 = __shfl_sync(0xffffffffu, o_l[0], lane & ~3);
        float l1 = __shfl_sync(0xffffffffu, o_l[2], lane & ~3);
        float inv0 = 1.f / l0, inv1 = 1.f / l1;
        const int qrl = w * 16 + (lane >> 2);
        #pragma unroll
        for (int nt = 0; nt < 8; nt++) {
            int col = h * HD + nt * 8 + (lane & 3) * 2;
            *(__half2*)(outh + (size_t)(q0 + qrl) * DM + col) =
                __floats2half2_rn(o[nt][0] * inv0, o[nt][1] * inv0);
            *(__half2*)(outh + (size_t)(q0 + qrl + 8) * DM + col) =
                __floats2half2_rn(o[nt][2] * inv1, o[nt][3] * inv1);
        }
        __syncthreads();
    }
}

// ---------------------------------------------------------------------------
// Launch
// ---------------------------------------------------------------------------
extern "C" void kernel_launch(void* const* d_in, const int* in_sizes, int n_in,
                              void* d_out, int out_size)
{
    const float* x    = (const float*)d_in[0];
    const float* Wqkv = (const float*)d_in[1];
    const float* bqkv = (const float*)d_in[2];
    const float* Wout = (const float*)d_in[3];
    const float* bout = (const float*)d_in[4];
    float* out = (float*)d_out;

    __half *xh, *wqkvh, *wouth, *qkv, *attn;
    cudaGetSymbolAddress((void**)&xh,    g_xh);
    cudaGetSymbolAddress((void**)&wqkvh, g_wqkvh);
    cudaGetSymbolAddress((void**)&wouth, g_wouth);
    cudaGetSymbolAddress((void**)&qkv,   g_qkv);
    cudaGetSymbolAddress((void**)&attn,  g_attn);

    // 0) fp32 -> fp16
    {
        int n4;
        n4 = SQ * DM / 4;
        conv_h<<<(n4 + 255) / 256, 256>>>((const float4*)x, (__half2*)xh, n4);
        n4 = DM * D3 / 4;
        conv_h<<<(n4 + 255) / 256, 256>>>((const float4*)Wqkv, (__half2*)wqkvh, n4);
        n4 = DM * DM / 4;
        conv_h<<<(n4 + 255) / 256, 256>>>((const float4*)Wout, (__half2*)wouth, n4);
    }

    // 1) QKV projection -> fp16 (also resets attention work queue)
    {
        cudaFuncSetAttribute(gemm_h<true>,
                             cudaFuncAttributeMaxDynamicSharedMemorySize, G_SMEM);
        dim3 grid(D3 / 128, SQ / 128);
        gemm_h<true><<<grid, 256, G_SMEM>>>(xh, wqkvh, bqkv, qkv, SQ, D3, DM);
    }

    // 2) Flash attention -> fp16 (persistent work-queue, 296 CTAs)
    {
        cudaFuncSetAttribute(attn_h,
                             cudaFuncAttributeMaxDynamicSharedMemorySize, AT_SMEM);
        attn_h<<<296, 256, AT_SMEM>>>(qkv, attn);
    }

    // 3) Output projection -> fp32
    {
        cudaFuncSetAttribute(gemm_h<false>,
                             cudaFuncAttributeMaxDynamicSharedMemorySize, G_SMEM);
        dim3 grid(DM / 128, SQ / 128);
        gemm_h<false><<<grid, 256, G_SMEM>>>(attn, wouth, bout, out, SQ, DM, DM);
    }
}